// round 7
// baseline (speedup 1.0000x reference)
#include <cuda_runtime.h>
#include <cuda_bf16.h>
#include <stdint.h>

#define BATCH 2
#define SEQ 2048
#define DM 1024
#define NH 16
#define DH 64
#define MTOT (BATCH*SEQ)
#define QSCALE 0.18033688f   // log2(e) / sqrt(64)

typedef __nv_bfloat16 bf16;

// ---------------- device-global scratch ----------------
__device__ __align__(16) bf16 g_xh[3ull*MTOT*DM], g_xl[3ull*MTOT*DM];
__device__ __align__(16) bf16 g_wth[3ull*DM*DM],  g_wtl[3ull*DM*DM];
__device__ __align__(16) bf16 g_woth[(size_t)DM*DM], g_wotl[(size_t)DM*DM];
__device__ __align__(16) bf16 g_qh[(size_t)MTOT*DM], g_ql[(size_t)MTOT*DM];
__device__ __align__(16) bf16 g_kh[(size_t)MTOT*DM], g_kl[(size_t)MTOT*DM];
__device__ __align__(16) bf16 g_vth[(size_t)MTOT*DM], g_vtl[(size_t)MTOT*DM]; // [bh*64+d][seq]
__device__ __align__(16) bf16 g_zh[(size_t)MTOT*DM], g_zl[(size_t)MTOT*DM];

// ---------------- helpers ----------------
__device__ __forceinline__ uint32_t smem_u32(const void* p) {
    uint32_t a;
    asm("{ .reg .u64 t; cvta.to.shared.u64 t, %1; cvt.u32.u64 %0, t; }" : "=r"(a) : "l"(p));
    return a;
}
#define SWZ128(o) ((o) ^ (((o) >> 3) & 0x70))

__device__ __forceinline__ void mma_bf16(float* c, const uint32_t* a, uint32_t b0, uint32_t b1) {
    asm volatile("mma.sync.aligned.m16n8k16.row.col.f32.bf16.bf16.f32 "
        "{%0,%1,%2,%3}, {%4,%5,%6,%7}, {%8,%9}, {%0,%1,%2,%3};"
        : "+f"(c[0]), "+f"(c[1]), "+f"(c[2]), "+f"(c[3])
        : "r"(a[0]), "r"(a[1]), "r"(a[2]), "r"(a[3]), "r"(b0), "r"(b1));
}
__device__ __forceinline__ void ldsm4(uint32_t* r, uint32_t a) {
    asm volatile("ldmatrix.sync.aligned.m8n8.x4.shared.b16 {%0,%1,%2,%3}, [%4];"
        : "=r"(r[0]), "=r"(r[1]), "=r"(r[2]), "=r"(r[3]) : "r"(a));
}
__device__ __forceinline__ uint32_t fraddr(uint32_t base, int lane, int r0, int ku) {
    int g = lane >> 3, r8 = lane & 7;
    return base + SWZ128(((r0 + r8 + ((g & 1) << 3)) << 7) + ((ku + (g >> 1)) << 4));
}
__device__ __forceinline__ float ex2f(float x) {
    float y; asm("ex2.approx.f32 %0, %1;" : "=f"(y) : "f"(x)); return y;
}
__device__ __forceinline__ void split2(float a, float b, uint32_t& hi, uint32_t& lo) {
    bf16 ah = __float2bfloat16(a), bh = __float2bfloat16(b);
    __nv_bfloat162 H; H.x = ah; H.y = bh;
    __nv_bfloat162 L;
    L.x = __float2bfloat16(a - __bfloat162float(ah));
    L.y = __float2bfloat16(b - __bfloat162float(bh));
    hi = *(uint32_t*)&H; lo = *(uint32_t*)&L;
}
__device__ __forceinline__ void cpa16(uint32_t dst, const void* src) {
    asm volatile("cp.async.cg.shared.global [%0], [%1], 16;" :: "r"(dst), "l"(src) : "memory");
}
#define CP_COMMIT() asm volatile("cp.async.commit_group;" ::: "memory")
#define CP_WAIT(n)  asm volatile("cp.async.wait_group %0;" :: "n"(n) : "memory")

// ---------------- conversion kernels ----------------
__global__ __launch_bounds__(256) void cvt_x_kernel(
    const float* __restrict__ q, const float* __restrict__ k, const float* __restrict__ v) {
    const int z = blockIdx.y;
    const float* __restrict__ src = (z == 0) ? q : (z == 1) ? k : v;
    size_t base = (size_t)z * MTOT * DM;
    size_t i = ((size_t)blockIdx.x * 256 + threadIdx.x) * 8;
    union { bf16 b[8]; uint4 u; } H, L;
    #pragma unroll
    for (int j = 0; j < 8; j += 4) {
        float4 f = *(const float4*)(src + i + j);
        float fv[4] = {f.x, f.y, f.z, f.w};
        #pragma unroll
        for (int q4 = 0; q4 < 4; q4++) {
            bf16 hh = __float2bfloat16(fv[q4]);
            H.b[j + q4] = hh;
            L.b[j + q4] = __float2bfloat16(fv[q4] - __bfloat162float(hh));
        }
    }
    *(uint4*)(g_xh + base + i) = H.u;
    *(uint4*)(g_xl + base + i) = L.u;
}

__global__ __launch_bounds__(256) void cvt_wqkv_kernel(
    const float* __restrict__ wq, const float* __restrict__ wk, const float* __restrict__ wv) {
    __shared__ float s[32][33];
    const int w = blockIdx.z >> 4, hh = blockIdx.z & 15;
    const float* __restrict__ W = ((w == 0) ? wq : (w == 1) ? wk : wv) + (size_t)hh * DM * DH;
    const int k0 = blockIdx.x * 32, e0 = blockIdx.y * 32;
    const int tx = threadIdx.x, ty = threadIdx.y;
    #pragma unroll
    for (int i = 0; i < 4; i++)
        s[ty + 8 * i][tx] = W[(size_t)(k0 + ty + 8 * i) * DH + e0 + tx];
    __syncthreads();
    size_t dbase = (size_t)w * DM * DM;
    #pragma unroll
    for (int i = 0; i < 4; i++) {
        float v = s[tx][ty + 8 * i];
        bf16 hi = __float2bfloat16(v);
        size_t o = dbase + (size_t)(hh * 64 + e0 + ty + 8 * i) * DM + k0 + tx;
        g_wth[o] = hi;
        g_wtl[o] = __float2bfloat16(v - __bfloat162float(hi));
    }
}

__global__ __launch_bounds__(256) void cvt_wo_kernel(const float* __restrict__ W) {
    __shared__ float s[32][33];
    const int k0 = blockIdx.x * 32, d0 = blockIdx.y * 32;
    const int tx = threadIdx.x, ty = threadIdx.y;
    #pragma unroll
    for (int i = 0; i < 4; i++)
        s[ty + 8 * i][tx] = W[(size_t)(k0 + ty + 8 * i) * DM + d0 + tx];
    __syncthreads();
    #pragma unroll
    for (int i = 0; i < 4; i++) {
        float v = s[tx][ty + 8 * i];
        bf16 hi = __float2bfloat16(v);
        size_t o = (size_t)(d0 + ty + 8 * i) * DM + k0 + tx;
        g_woth[o] = hi;
        g_wotl[o] = __float2bfloat16(v - __bfloat162float(hi));
    }
}

// ---------------- split-bf16 GEMM: C[256x128] = X @ Wt^T (+bias) ----------------
// 512 threads (16 warps: 8M x 2N; warp tile 32m x 64n). K-chunk 64.
// Stage 96KB: A_hi@0 A_lo@32K B_hi@64K B_lo@80K. 2 stages = 192KB dynamic.
#define PJ_AH 0
#define PJ_AL 32768
#define PJ_BH 65536
#define PJ_BL 81920
#define PJ_STAGE 98304

__device__ __forceinline__ void proj_copy(
    const bf16* __restrict__ Xh, const bf16* __restrict__ Xl,
    const bf16* __restrict__ Wh, const bf16* __restrict__ Wl,
    uint32_t sb, int st, int m0, int n0, int k0, int t)
{
    #pragma unroll
    for (int u = 0; u < 8; u++) {                    // A: 256 rows, hi+lo
        int idx = u * 512 + t;
        int sp = idx >> 11, row = (idx >> 3) & 255, c = idx & 7;
        uint32_t so = SWZ128((row << 7) + (c << 4));
        cpa16(sb + st + (sp ? PJ_AL : PJ_AH) + so,
              (sp ? Xl : Xh) + (size_t)(m0 + row) * DM + k0 + c * 8);
    }
    #pragma unroll
    for (int u = 0; u < 4; u++) {                    // B: 128 rows, hi+lo
        int idx = u * 512 + t;
        int sp = idx >> 10, row = (idx >> 3) & 127, c = idx & 7;
        uint32_t so = SWZ128((row << 7) + (c << 4));
        cpa16(sb + st + (sp ? PJ_BL : PJ_BH) + so,
              (sp ? Wl : Wh) + (size_t)(n0 + row) * DM + k0 + c * 8);
    }
}

__device__ __forceinline__ void proj_compute(uint32_t sb, int st, int lane,
                                             int wm, int wn, float acc[2][8][4])
{
    #pragma unroll
    for (int ks = 0; ks < 4; ks++) {
        uint32_t aH[2][4], aL[2][4];
        #pragma unroll
        for (int mt = 0; mt < 2; mt++) {
            ldsm4(aH[mt], fraddr(sb + st + PJ_AH, lane, wm + mt * 16, 2 * ks));
            ldsm4(aL[mt], fraddr(sb + st + PJ_AL, lane, wm + mt * 16, 2 * ks));
        }
        #pragma unroll
        for (int np = 0; np < 4; np++) {
            uint32_t bH[4], bL[4];
            ldsm4(bH, fraddr(sb + st + PJ_BH, lane, wn + np * 16, 2 * ks));
            ldsm4(bL, fraddr(sb + st + PJ_BL, lane, wn + np * 16, 2 * ks));
            #pragma unroll
            for (int mt = 0; mt < 2; mt++) {
                mma_bf16(acc[mt][2*np],   aH[mt], bH[0], bH[2]);
                mma_bf16(acc[mt][2*np+1], aH[mt], bH[1], bH[3]);
                mma_bf16(acc[mt][2*np],   aH[mt], bL[0], bL[2]);
                mma_bf16(acc[mt][2*np+1], aH[mt], bL[1], bL[3]);
                mma_bf16(acc[mt][2*np],   aL[mt], bH[0], bH[2]);
                mma_bf16(acc[mt][2*np+1], aL[mt], bH[1], bH[3]);
            }
        }
    }
}

// mode: 0=Q (scale, split out), 1=K (split out), 2=V (transposed split out), 3=fp32 out
__device__ __forceinline__ void proj_core(
    const bf16* __restrict__ Xh, const bf16* __restrict__ Xl,
    const bf16* __restrict__ Wh, const bf16* __restrict__ Wl,
    const float* __restrict__ bias,
    bf16* __restrict__ Oh, bf16* __restrict__ Ol, float* __restrict__ Of,
    char* sm, int m0, int n0, int mode)
{
    const int t = threadIdx.x, lane = t & 31, w = t >> 5;
    const uint32_t sb = smem_u32(sm);
    const int wm = (w & 7) * 32, wn = (w >> 3) * 64;
    float acc[2][8][4] = {};

    proj_copy(Xh, Xl, Wh, Wl, sb, 0, m0, n0, 0, t);
    CP_COMMIT();

    for (int kc = 0; kc < 16; kc++) {
        if (kc + 1 < 16) {
            proj_copy(Xh, Xl, Wh, Wl, sb, ((kc + 1) & 1) * PJ_STAGE, m0, n0, (kc + 1) * 64, t);
            CP_COMMIT();
            CP_WAIT(1);
        } else {
            CP_WAIT(0);
        }
        __syncthreads();
        proj_compute(sb, (kc & 1) * PJ_STAGE, lane, wm, wn, acc);
        __syncthreads();
    }

    const float scale = (mode == 0) ? QSCALE : 1.0f;
    #pragma unroll
    for (int mt = 0; mt < 2; mt++)
        #pragma unroll
        for (int np = 0; np < 8; np++)
            #pragma unroll
            for (int h2 = 0; h2 < 2; h2++) {
                int m = m0 + wm + mt * 16 + (lane >> 2) + h2 * 8;
                int n = n0 + wn + np * 8 + 2 * (lane & 3);
                float v0 = (acc[mt][np][h2 * 2]     + bias[n])     * scale;
                float v1 = (acc[mt][np][h2 * 2 + 1] + bias[n + 1]) * scale;
                if (mode == 3) {
                    *(float2*)(Of + (size_t)m * DM + n) = make_float2(v0, v1);
                } else if (mode == 2) {
                    int bb = m >> 11, seq = m & 2047;
                    bf16 h0 = __float2bfloat16(v0), h1 = __float2bfloat16(v1);
                    size_t o0 = ((size_t)(bb * NH + (n >> 6)) * DH + (n & 63)) * SEQ + seq;
                    size_t o1 = ((size_t)(bb * NH + ((n+1) >> 6)) * DH + ((n+1) & 63)) * SEQ + seq;
                    Oh[o0] = h0; Ol[o0] = __float2bfloat16(v0 - __bfloat162float(h0));
                    Oh[o1] = h1; Ol[o1] = __float2bfloat16(v1 - __bfloat162float(h1));
                } else {
                    uint32_t hi, lo;
                    split2(v0, v1, hi, lo);
                    *(uint32_t*)(Oh + (size_t)m * DM + n) = hi;
                    *(uint32_t*)(Ol + (size_t)m * DM + n) = lo;
                }
            }
}

__global__ __launch_bounds__(512, 1) void qkv_proj_mma(const float* bq, const float* bk,
                                                       const float* bv) {
    extern __shared__ char sm[];
    const int z = blockIdx.z;
    proj_core(g_xh + (size_t)z * MTOT * DM, g_xl + (size_t)z * MTOT * DM,
              g_wth + (size_t)z * DM * DM, g_wtl + (size_t)z * DM * DM,
              (z == 0) ? bq : (z == 1) ? bk : bv,
              (z == 0) ? g_qh : (z == 1) ? g_kh : g_vth,
              (z == 0) ? g_ql : (z == 1) ? g_kl : g_vtl,
              nullptr, sm, blockIdx.y * 256, blockIdx.x * 128, z);
}

__global__ __launch_bounds__(512, 1) void out_proj_mma(const float* bo, float* out) {
    extern __shared__ char sm[];
    proj_core(g_zh, g_zl, g_woth, g_wotl, bo, nullptr, nullptr, out,
              sm, blockIdx.y * 256, blockIdx.x * 128, 3);
}

// ---------------- FA2 attention: 512 threads, q-tile 256, 3 K/V stages ----------------
// CTA = (qb, head, batch), 16 warps x 16 q-rows, key-tile 64.
// smem: Q_hi@0 Q_lo@32K; stage s @ 64K+32K*s: K_hi 0, K_lo 8K, V_hi 16K, V_lo 24K. 160KB.
#define AT_QL  32768
#define AT_ST0 65536
#define AT_SS  32768

__device__ __forceinline__ void attn_copy(uint32_t sb, int kb, int b, int hd, int t) {
    const int st = AT_ST0 + (kb % 3) * AT_SS;
    const int k0 = kb * 64;
    #pragma unroll
    for (int u = 0; u < 2; u++) {
        int idx = u * 512 + t;
        int sp = idx >> 9, row = (idx >> 3) & 63, c = idx & 7;
        uint32_t so = SWZ128((row << 7) + (c << 4));
        cpa16(sb + st + sp * 8192 + so,
              (sp ? g_kl : g_kh) + (size_t)(b * SEQ + k0 + row) * DM + hd * DH + c * 8);
        cpa16(sb + st + 16384 + sp * 8192 + so,
              (sp ? g_vtl : g_vth) + ((size_t)((b * NH + hd) * DH + row)) * SEQ + k0 + c * 8);
    }
}

__global__ __launch_bounds__(512, 1) void attn_mma() {
    extern __shared__ char sm[];
    const uint32_t sb = smem_u32(sm);
    const int t = threadIdx.x, lane = t & 31, w = t >> 5;
    const int qb = (gridDim.x - 1) - blockIdx.x;    // largest-first
    const int hd = blockIdx.y, b = blockIdx.z;
    const int q0 = qb * 256, wq = w * 16;
    const int nkb = 4 * qb + 4;

    attn_copy(sb, 0, b, hd, t);
    CP_COMMIT();
    attn_copy(sb, 1, b, hd, t);
    CP_COMMIT();

    // Q tile (256 x 64, hi/lo), plain stores (512 threads: row = t>>1, split = t&1)
    {
        int r = t >> 1, s = t & 1;
        const bf16* __restrict__ src =
            (s ? g_ql : g_qh) + (size_t)(b * SEQ + q0 + r) * DM + hd * DH;
        char* dst = sm + (s ? AT_QL : 0);
        #pragma unroll
        for (int i = 0; i < 8; i++)
            *(uint4*)(dst + SWZ128((r << 7) + (i << 4))) = *(const uint4*)(src + i * 8);
    }
    __syncthreads();

    uint32_t qH[4][4], qL[4][4];
    #pragma unroll
    for (int ks = 0; ks < 4; ks++) {
        ldsm4(qH[ks], fraddr(sb,         lane, wq, 2 * ks));
        ldsm4(qL[ks], fraddr(sb + AT_QL, lane, wq, 2 * ks));
    }

    float oacc[8][4] = {};
    float lsum[2] = {0.0f, 0.0f};

    for (int kb = 0; kb < nkb; kb++) {
        const int k0 = kb * 64;
        const int st = AT_ST0 + (kb % 3) * AT_SS;

        if (kb + 2 < nkb) {
            attn_copy(sb, kb + 2, b, hd, t);   // stage freed by end-of-iter sync
            CP_COMMIT();
            CP_WAIT(2);
        } else if (kb + 1 < nkb) {
            CP_WAIT(1);
        } else {
            CP_WAIT(0);
        }
        __syncthreads();

        // S = Q K^T (3 split terms)
        float sacc[8][4] = {};
        #pragma unroll
        for (int ds = 0; ds < 4; ds++)
            #pragma unroll
            for (int np = 0; np < 4; np++) {
                uint32_t kH[4], kL[4];
                ldsm4(kH, fraddr(sb + st,        lane, np * 16, 2 * ds));
                ldsm4(kL, fraddr(sb + st + 8192, lane, np * 16, 2 * ds));
                mma_bf16(sacc[2*np],   qH[ds], kH[0], kH[2]);
                mma_bf16(sacc[2*np+1], qH[ds], kH[1], kH[3]);
                mma_bf16(sacc[2*np],   qH[ds], kL[0], kL[2]);
                mma_bf16(sacc[2*np+1], qH[ds], kL[1], kL[3]);
                mma_bf16(sacc[2*np],   qL[ds], kH[0], kH[2]);
                mma_bf16(sacc[2*np+1], qL[ds], kH[1], kH[3]);
            }

        // exp + mask (scores pre-scaled by log2e/8 via Q epilogue)
        if (kb >= 4 * qb) {
            #pragma unroll
            for (int np = 0; np < 8; np++)
                #pragma unroll
                for (int j = 0; j < 4; j++) {
                    int kg = k0 + np * 8 + 2 * (lane & 3) + (j & 1);
                    int qg = q0 + wq + (lane >> 2) + (j >> 1) * 8;
                    float p = (kg <= qg) ? ex2f(sacc[np][j]) : 0.0f;
                    lsum[j >> 1] += p;
                    sacc[np][j] = p;
                }
        } else {
            #pragma unroll
            for (int np = 0; np < 8; np++)
                #pragma unroll
                for (int j = 0; j < 4; j++) {
                    float p = ex2f(sacc[np][j]);
                    lsum[j >> 1] += p;
                    sacc[np][j] = p;
                }
        }

        // P (C-frag -> A-frag split) and PV from stage kb
        #pragma unroll
        for (int ks = 0; ks < 4; ks++) {
            uint32_t pH[4], pL[4];
            split2(sacc[2*ks][0],   sacc[2*ks][1],   pH[0], pL[0]);
            split2(sacc[2*ks][2],   sacc[2*ks][3],   pH[1], pL[1]);
            split2(sacc[2*ks+1][0], sacc[2*ks+1][1], pH[2], pL[2]);
            split2(sacc[2*ks+1][2], sacc[2*ks+1][3], pH[3], pL[3]);
            #pragma unroll
            for (int dp = 0; dp < 4; dp++) {
                uint32_t vH[4], vL[4];
                ldsm4(vH, fraddr(sb + st + 16384, lane, dp * 16, 2 * ks));
                ldsm4(vL, fraddr(sb + st + 24576, lane, dp * 16, 2 * ks));
                mma_bf16(oacc[2*dp],   pH, vH[0], vH[2]);
                mma_bf16(oacc[2*dp+1], pH, vH[1], vH[3]);
                mma_bf16(oacc[2*dp],   pH, vL[0], vL[2]);
                mma_bf16(oacc[2*dp+1], pH, vL[1], vL[3]);
                mma_bf16(oacc[2*dp],   pL, vH[0], vH[2]);
                mma_bf16(oacc[2*dp+1], pL, vH[1], vH[3]);
            }
        }
        __syncthreads();   // all reads done before stage reuse next iters
    }

    #pragma unroll
    for (int i = 0; i < 2; i++) {
        lsum[i] += __shfl_xor_sync(0xffffffffu, lsum[i], 1);
        lsum[i] += __shfl_xor_sync(0xffffffffu, lsum[i], 2);
    }
    float inv0 = 1.0f / lsum[0], inv1 = 1.0f / lsum[1];

    #pragma unroll
    for (int np = 0; np < 8; np++)
        #pragma unroll
        for (int h2 = 0; h2 < 2; h2++) {
            int q = q0 + wq + (lane >> 2) + h2 * 8;
            int d = np * 8 + 2 * (lane & 3);
            float inv = h2 ? inv1 : inv0;
            float v0 = oacc[np][h2 * 2] * inv;
            float v1 = oacc[np][h2 * 2 + 1] * inv;
            uint32_t hi, lo;
            split2(v0, v1, hi, lo);
            size_t o = (size_t)(b * SEQ + q) * DM + hd * DH + d;
            *(uint32_t*)(g_zh + o) = hi;
            *(uint32_t*)(g_zl + o) = lo;
        }
}

// ---------------------------------------------------------------------------
extern "C" void kernel_launch(void* const* d_in, const int* in_sizes, int n_in,
                              void* d_out, int out_size)
{
    const float* qin = (const float*)d_in[0];
    const float* kin = (const float*)d_in[1];
    const float* vin = (const float*)d_in[2];
    const float* WQ  = (const float*)d_in[3];
    const float* WK  = (const float*)d_in[4];
    const float* WV  = (const float*)d_in[5];
    const float* WO  = (const float*)d_in[6];
    const float* bQ  = (const float*)d_in[7];
    const float* bK  = (const float*)d_in[8];
    const float* bV  = (const float*)d_in[9];
    const float* bO  = (const float*)d_in[10];
    float* out = (float*)d_out;

    cudaFuncSetAttribute(qkv_proj_mma, cudaFuncAttributeMaxDynamicSharedMemorySize, 196608);
    cudaFuncSetAttribute(out_proj_mma, cudaFuncAttributeMaxDynamicSharedMemorySize, 196608);
    cudaFuncSetAttribute(attn_mma,     cudaFuncAttributeMaxDynamicSharedMemorySize, 163840);

    cvt_x_kernel<<<dim3(MTOT * DM / 8 / 256, 3), 256>>>(qin, kin, vin);
    cvt_wqkv_kernel<<<dim3(32, 2, 48), dim3(32, 8)>>>(WQ, WK, WV);
    cvt_wo_kernel<<<dim3(32, 32), dim3(32, 8)>>>(WO);

    qkv_proj_mma<<<dim3(DM / 128, MTOT / 256, 3), 512, 196608>>>(bQ, bK, bV);
    attn_mma<<<dim3(SEQ / 256, NH, BATCH), 512, 163840>>>();
    out_proj_mma<<<dim3(DM / 128, MTOT / 256), 512, 196608>>>(bO, out);
}

// round 8
// speedup vs baseline: 1.1268x; 1.1268x over previous
#include <cuda_runtime.h>
#include <cuda_bf16.h>
#include <stdint.h>

#define BATCH 2
#define SEQ 2048
#define DM 1024
#define NH 16
#define DH 64
#define MTOT (BATCH*SEQ)
#define QSCALE 0.18033688f   // log2(e) / sqrt(64)

typedef __nv_bfloat16 bf16;

// ---------------- device-global scratch ----------------
__device__ __align__(16) bf16 g_xh[3ull*MTOT*DM], g_xl[3ull*MTOT*DM];
__device__ __align__(16) bf16 g_wth[3ull*DM*DM],  g_wtl[3ull*DM*DM];
__device__ __align__(16) bf16 g_woth[(size_t)DM*DM], g_wotl[(size_t)DM*DM];
__device__ __align__(16) bf16 g_qh[(size_t)MTOT*DM], g_ql[(size_t)MTOT*DM];
__device__ __align__(16) bf16 g_kh[(size_t)MTOT*DM], g_kl[(size_t)MTOT*DM];
__device__ __align__(16) bf16 g_vth[(size_t)MTOT*DM], g_vtl[(size_t)MTOT*DM]; // [bh*64+d][seq]
__device__ __align__(16) bf16 g_zh[(size_t)MTOT*DM], g_zl[(size_t)MTOT*DM];

// ---------------- helpers ----------------
__device__ __forceinline__ uint32_t smem_u32(const void* p) {
    uint32_t a;
    asm("{ .reg .u64 t; cvta.to.shared.u64 t, %1; cvt.u32.u64 %0, t; }" : "=r"(a) : "l"(p));
    return a;
}
#define SWZ128(o) ((o) ^ (((o) >> 3) & 0x70))

__device__ __forceinline__ void mma_bf16(float* c, const uint32_t* a, uint32_t b0, uint32_t b1) {
    asm volatile("mma.sync.aligned.m16n8k16.row.col.f32.bf16.bf16.f32 "
        "{%0,%1,%2,%3}, {%4,%5,%6,%7}, {%8,%9}, {%0,%1,%2,%3};"
        : "+f"(c[0]), "+f"(c[1]), "+f"(c[2]), "+f"(c[3])
        : "r"(a[0]), "r"(a[1]), "r"(a[2]), "r"(a[3]), "r"(b0), "r"(b1));
}
__device__ __forceinline__ void ldsm4(uint32_t* r, uint32_t a) {
    asm volatile("ldmatrix.sync.aligned.m8n8.x4.shared.b16 {%0,%1,%2,%3}, [%4];"
        : "=r"(r[0]), "=r"(r[1]), "=r"(r[2]), "=r"(r[3]) : "r"(a));
}
__device__ __forceinline__ uint32_t fraddr(uint32_t base, int lane, int r0, int ku) {
    int g = lane >> 3, r8 = lane & 7;
    return base + SWZ128(((r0 + r8 + ((g & 1) << 3)) << 7) + ((ku + (g >> 1)) << 4));
}
__device__ __forceinline__ float ex2f(float x) {
    float y; asm("ex2.approx.f32 %0, %1;" : "=f"(y) : "f"(x)); return y;
}
__device__ __forceinline__ void split2(float a, float b, uint32_t& hi, uint32_t& lo) {
    bf16 ah = __float2bfloat16(a), bh = __float2bfloat16(b);
    __nv_bfloat162 H; H.x = ah; H.y = bh;
    __nv_bfloat162 L;
    L.x = __float2bfloat16(a - __bfloat162float(ah));
    L.y = __float2bfloat16(b - __bfloat162float(bh));
    hi = *(uint32_t*)&H; lo = *(uint32_t*)&L;
}
__device__ __forceinline__ void cpa16(uint32_t dst, const void* src) {
    asm volatile("cp.async.cg.shared.global [%0], [%1], 16;" :: "r"(dst), "l"(src) : "memory");
}
#define CP_COMMIT() asm volatile("cp.async.commit_group;" ::: "memory")
#define CP_WAIT(n)  asm volatile("cp.async.wait_group %0;" :: "n"(n) : "memory")

// ---------------- conversion kernels ----------------
__global__ __launch_bounds__(256) void cvt_x_kernel(
    const float* __restrict__ q, const float* __restrict__ k, const float* __restrict__ v) {
    const int z = blockIdx.y;
    const float* __restrict__ src = (z == 0) ? q : (z == 1) ? k : v;
    size_t base = (size_t)z * MTOT * DM;
    size_t i = ((size_t)blockIdx.x * 256 + threadIdx.x) * 8;
    union { bf16 b[8]; uint4 u; } H, L;
    #pragma unroll
    for (int j = 0; j < 8; j += 4) {
        float4 f = *(const float4*)(src + i + j);
        float fv[4] = {f.x, f.y, f.z, f.w};
        #pragma unroll
        for (int q4 = 0; q4 < 4; q4++) {
            bf16 hh = __float2bfloat16(fv[q4]);
            H.b[j + q4] = hh;
            L.b[j + q4] = __float2bfloat16(fv[q4] - __bfloat162float(hh));
        }
    }
    *(uint4*)(g_xh + base + i) = H.u;
    *(uint4*)(g_xl + base + i) = L.u;
}

__global__ __launch_bounds__(256) void cvt_wqkv_kernel(
    const float* __restrict__ wq, const float* __restrict__ wk, const float* __restrict__ wv) {
    __shared__ float s[32][33];
    const int w = blockIdx.z >> 4, hh = blockIdx.z & 15;
    const float* __restrict__ W = ((w == 0) ? wq : (w == 1) ? wk : wv) + (size_t)hh * DM * DH;
    const int k0 = blockIdx.x * 32, e0 = blockIdx.y * 32;
    const int tx = threadIdx.x, ty = threadIdx.y;
    #pragma unroll
    for (int i = 0; i < 4; i++)
        s[ty + 8 * i][tx] = W[(size_t)(k0 + ty + 8 * i) * DH + e0 + tx];
    __syncthreads();
    size_t dbase = (size_t)w * DM * DM;
    #pragma unroll
    for (int i = 0; i < 4; i++) {
        float v = s[tx][ty + 8 * i];
        bf16 hi = __float2bfloat16(v);
        size_t o = dbase + (size_t)(hh * 64 + e0 + ty + 8 * i) * DM + k0 + tx;
        g_wth[o] = hi;
        g_wtl[o] = __float2bfloat16(v - __bfloat162float(hi));
    }
}

__global__ __launch_bounds__(256) void cvt_wo_kernel(const float* __restrict__ W) {
    __shared__ float s[32][33];
    const int k0 = blockIdx.x * 32, d0 = blockIdx.y * 32;
    const int tx = threadIdx.x, ty = threadIdx.y;
    #pragma unroll
    for (int i = 0; i < 4; i++)
        s[ty + 8 * i][tx] = W[(size_t)(k0 + ty + 8 * i) * DM + d0 + tx];
    __syncthreads();
    #pragma unroll
    for (int i = 0; i < 4; i++) {
        float v = s[tx][ty + 8 * i];
        bf16 hi = __float2bfloat16(v);
        size_t o = (size_t)(d0 + ty + 8 * i) * DM + k0 + tx;
        g_woth[o] = hi;
        g_wotl[o] = __float2bfloat16(v - __bfloat162float(hi));
    }
}

// ---------------- split-bf16 GEMM: C[128x128] = X @ Wt^T (+bias) ----------------
// 256 threads (8 warps: 4M x 2N; warp tile 32m x 64n). K-chunk 64.
// Stage 64KB: A_hi@0 A_lo@16K B_hi@32K B_lo@48K. 2 stages = 128KB dynamic.
#define PJ_STAGE 65536

__device__ __forceinline__ void proj_copy(
    const bf16* __restrict__ Xh, const bf16* __restrict__ Xl,
    const bf16* __restrict__ Wh, const bf16* __restrict__ Wl,
    uint32_t sb, int st, int m0, int n0, int k0, int t)
{
    #pragma unroll
    for (int u = 0; u < 8; u++) {
        int idx = u * 256 + t;
        int sp = idx >> 10, row = (idx >> 3) & 127, c = idx & 7;
        uint32_t so = SWZ128((row << 7) + (c << 4));
        cpa16(sb + st + sp * 16384 + so,
              (sp ? Xl : Xh) + (size_t)(m0 + row) * DM + k0 + c * 8);
        cpa16(sb + st + 32768 + sp * 16384 + so,
              (sp ? Wl : Wh) + (size_t)(n0 + row) * DM + k0 + c * 8);
    }
}

// term-pass order: (aH*bH over np) -> (aL*bH, reuse bH frags) -> (aH*bL).
// Same-acc reuse distance = 16 MMAs (was 2).
__device__ __forceinline__ void proj_compute(uint32_t sb, int st, int lane,
                                             int wm, int wn, float acc[2][8][4])
{
    #pragma unroll
    for (int ks = 0; ks < 4; ks++) {
        uint32_t aH[2][4], aL[2][4], bH[4][4];
        #pragma unroll
        for (int mt = 0; mt < 2; mt++) {
            ldsm4(aH[mt], fraddr(sb + st,         lane, wm + mt * 16, 2 * ks));
            ldsm4(aL[mt], fraddr(sb + st + 16384, lane, wm + mt * 16, 2 * ks));
        }
        #pragma unroll
        for (int np = 0; np < 4; np++) {              // pass 1: aH * bH
            ldsm4(bH[np], fraddr(sb + st + 32768, lane, wn + np * 16, 2 * ks));
            mma_bf16(acc[0][2*np],   aH[0], bH[np][0], bH[np][2]);
            mma_bf16(acc[0][2*np+1], aH[0], bH[np][1], bH[np][3]);
            mma_bf16(acc[1][2*np],   aH[1], bH[np][0], bH[np][2]);
            mma_bf16(acc[1][2*np+1], aH[1], bH[np][1], bH[np][3]);
        }
        #pragma unroll
        for (int np = 0; np < 4; np++) {              // pass 2: aL * bH
            mma_bf16(acc[0][2*np],   aL[0], bH[np][0], bH[np][2]);
            mma_bf16(acc[0][2*np+1], aL[0], bH[np][1], bH[np][3]);
            mma_bf16(acc[1][2*np],   aL[1], bH[np][0], bH[np][2]);
            mma_bf16(acc[1][2*np+1], aL[1], bH[np][1], bH[np][3]);
        }
        #pragma unroll
        for (int np = 0; np < 4; np++) {              // pass 3: aH * bL
            uint32_t bL[4];
            ldsm4(bL, fraddr(sb + st + 49152, lane, wn + np * 16, 2 * ks));
            mma_bf16(acc[0][2*np],   aH[0], bL[0], bL[2]);
            mma_bf16(acc[0][2*np+1], aH[0], bL[1], bL[3]);
            mma_bf16(acc[1][2*np],   aH[1], bL[0], bL[2]);
            mma_bf16(acc[1][2*np+1], aH[1], bL[1], bL[3]);
        }
    }
}

// mode: 0=Q (scale, split out), 1=K (split out), 2=V (transposed split out), 3=fp32 out
__device__ __forceinline__ void proj_core(
    const bf16* __restrict__ Xh, const bf16* __restrict__ Xl,
    const bf16* __restrict__ Wh, const bf16* __restrict__ Wl,
    const float* __restrict__ bias,
    bf16* __restrict__ Oh, bf16* __restrict__ Ol, float* __restrict__ Of,
    char* sm, int m0, int n0, int mode)
{
    const int t = threadIdx.x, lane = t & 31, w = t >> 5;
    const uint32_t sb = smem_u32(sm);
    const int wm = (w & 3) * 32, wn = (w >> 2) * 64;
    float acc[2][8][4] = {};

    proj_copy(Xh, Xl, Wh, Wl, sb, 0, m0, n0, 0, t);
    CP_COMMIT();

    for (int kc = 0; kc < 16; kc++) {
        if (kc + 1 < 16) {
            proj_copy(Xh, Xl, Wh, Wl, sb, ((kc + 1) & 1) * PJ_STAGE, m0, n0, (kc + 1) * 64, t);
            CP_COMMIT();
            CP_WAIT(1);
        } else {
            CP_WAIT(0);
        }
        __syncthreads();
        proj_compute(sb, (kc & 1) * PJ_STAGE, lane, wm, wn, acc);
        __syncthreads();
    }

    const float scale = (mode == 0) ? QSCALE : 1.0f;
    #pragma unroll
    for (int mt = 0; mt < 2; mt++)
        #pragma unroll
        for (int np = 0; np < 8; np++)
            #pragma unroll
            for (int h2 = 0; h2 < 2; h2++) {
                int m = m0 + wm + mt * 16 + (lane >> 2) + h2 * 8;
                int n = n0 + wn + np * 8 + 2 * (lane & 3);
                float v0 = (acc[mt][np][h2 * 2]     + bias[n])     * scale;
                float v1 = (acc[mt][np][h2 * 2 + 1] + bias[n + 1]) * scale;
                if (mode == 3) {
                    *(float2*)(Of + (size_t)m * DM + n) = make_float2(v0, v1);
                } else if (mode == 2) {
                    int bb = m >> 11, seq = m & 2047;
                    bf16 h0 = __float2bfloat16(v0), h1 = __float2bfloat16(v1);
                    size_t o0 = ((size_t)(bb * NH + (n >> 6)) * DH + (n & 63)) * SEQ + seq;
                    size_t o1 = ((size_t)(bb * NH + ((n+1) >> 6)) * DH + ((n+1) & 63)) * SEQ + seq;
                    Oh[o0] = h0; Ol[o0] = __float2bfloat16(v0 - __bfloat162float(h0));
                    Oh[o1] = h1; Ol[o1] = __float2bfloat16(v1 - __bfloat162float(h1));
                } else {
                    uint32_t hi, lo;
                    split2(v0, v1, hi, lo);
                    *(uint32_t*)(Oh + (size_t)m * DM + n) = hi;
                    *(uint32_t*)(Ol + (size_t)m * DM + n) = lo;
                }
            }
}

__global__ __launch_bounds__(256, 1) void qkv_proj_mma(const float* bq, const float* bk,
                                                       const float* bv) {
    extern __shared__ char sm[];
    const int z = blockIdx.z;
    proj_core(g_xh + (size_t)z * MTOT * DM, g_xl + (size_t)z * MTOT * DM,
              g_wth + (size_t)z * DM * DM, g_wtl + (size_t)z * DM * DM,
              (z == 0) ? bq : (z == 1) ? bk : bv,
              (z == 0) ? g_qh : (z == 1) ? g_kh : g_vth,
              (z == 0) ? g_ql : (z == 1) ? g_kl : g_vtl,
              nullptr, sm, blockIdx.y * 128, blockIdx.x * 128, z);
}

__global__ __launch_bounds__(256, 1) void out_proj_mma(const float* bo, float* out) {
    extern __shared__ char sm[];
    proj_core(g_zh, g_zl, g_woth, g_wotl, bo, nullptr, nullptr, out,
              sm, blockIdx.y * 128, blockIdx.x * 128, 3);
}

// ---------------- FA2 attention: q-tile 128, 256 threads, 2-stage K/V ----------------
// smem: Q_hi@0 Q_lo@16K; stage s @ 32K+32K*s: K_hi 0, K_lo 8K, V_hi 16K, V_lo 24K. 96KB.
#define AT_ST0 32768
#define AT_SS  32768

__device__ __forceinline__ void attn_copy(uint32_t sb, int kb, int b, int hd, int t) {
    const int st = AT_ST0 + (kb & 1) * AT_SS;
    const int k0 = kb * 64;
    #pragma unroll
    for (int u = 0; u < 4; u++) {
        int idx = u * 256 + t;
        int sp = idx >> 9, row = (idx >> 3) & 63, c = idx & 7;
        uint32_t so = SWZ128((row << 7) + (c << 4));
        cpa16(sb + st + sp * 8192 + so,
              (sp ? g_kl : g_kh) + (size_t)(b * SEQ + k0 + row) * DM + hd * DH + c * 8);
        cpa16(sb + st + 16384 + sp * 8192 + so,
              (sp ? g_vtl : g_vth) + ((size_t)((b * NH + hd) * DH + row)) * SEQ + k0 + c * 8);
    }
}

__global__ __launch_bounds__(256, 1) void attn_mma() {
    extern __shared__ char sm[];
    const uint32_t sb = smem_u32(sm);
    const int t = threadIdx.x, lane = t & 31, w = t >> 5;
    const int qb = (gridDim.x - 1) - blockIdx.x;    // largest-first
    const int hd = blockIdx.y, b = blockIdx.z;
    const int q0 = qb * 128, wq = w * 16;
    const int nkb = 2 * qb + 2;

    attn_copy(sb, 0, b, hd, t);
    CP_COMMIT();

    // Q tile (128 x 64, hi/lo), plain stores
    {
        int r = t >> 1, s = t & 1;
        const bf16* __restrict__ src =
            (s ? g_ql : g_qh) + (size_t)(b * SEQ + q0 + r) * DM + hd * DH;
        char* dst = sm + (s ? 16384 : 0);
        #pragma unroll
        for (int i = 0; i < 8; i++)
            *(uint4*)(dst + SWZ128((r << 7) + (i << 4))) = *(const uint4*)(src + i * 8);
    }
    __syncthreads();

    uint32_t qH[4][4], qL[4][4];
    #pragma unroll
    for (int ks = 0; ks < 4; ks++) {
        ldsm4(qH[ks], fraddr(sb,         lane, wq, 2 * ks));
        ldsm4(qL[ks], fraddr(sb + 16384, lane, wq, 2 * ks));
    }

    float oacc[8][4] = {};
    float lsum[2] = {0.0f, 0.0f};

    for (int kb = 0; kb < nkb; kb++) {
        const int k0 = kb * 64;
        const int st = AT_ST0 + (kb & 1) * AT_SS;
        if (kb + 1 < nkb) {
            attn_copy(sb, kb + 1, b, hd, t);
            CP_COMMIT();
            CP_WAIT(1);
        } else {
            CP_WAIT(0);
        }
        __syncthreads();

        // S = Q K^T: term passes (qH*kH, qL*kH reuse, qH*kL)
        float sacc[8][4] = {};
        #pragma unroll
        for (int ds = 0; ds < 4; ds++) {
            uint32_t kH[4][4];
            #pragma unroll
            for (int np = 0; np < 4; np++) {
                ldsm4(kH[np], fraddr(sb + st, lane, np * 16, 2 * ds));
                mma_bf16(sacc[2*np],   qH[ds], kH[np][0], kH[np][2]);
                mma_bf16(sacc[2*np+1], qH[ds], kH[np][1], kH[np][3]);
            }
            #pragma unroll
            for (int np = 0; np < 4; np++) {
                mma_bf16(sacc[2*np],   qL[ds], kH[np][0], kH[np][2]);
                mma_bf16(sacc[2*np+1], qL[ds], kH[np][1], kH[np][3]);
            }
            #pragma unroll
            for (int np = 0; np < 4; np++) {
                uint32_t kL[4];
                ldsm4(kL, fraddr(sb + st + 8192, lane, np * 16, 2 * ds));
                mma_bf16(sacc[2*np],   qH[ds], kL[0], kL[2]);
                mma_bf16(sacc[2*np+1], qH[ds], kL[1], kL[3]);
            }
        }

        // exp + mask (scores pre-scaled by log2e/8 via Q epilogue)
        if (kb >= 2 * qb) {
            #pragma unroll
            for (int np = 0; np < 8; np++)
                #pragma unroll
                for (int j = 0; j < 4; j++) {
                    int kg = k0 + np * 8 + 2 * (lane & 3) + (j & 1);
                    int qg = q0 + wq + (lane >> 2) + (j >> 1) * 8;
                    float p = (kg <= qg) ? ex2f(sacc[np][j]) : 0.0f;
                    lsum[j >> 1] += p;
                    sacc[np][j] = p;
                }
        } else {
            #pragma unroll
            for (int np = 0; np < 8; np++)
                #pragma unroll
                for (int j = 0; j < 4; j++) {
                    float p = ex2f(sacc[np][j]);
                    lsum[j >> 1] += p;
                    sacc[np][j] = p;
                }
        }

        // PV: term passes (pH*vH, pL*vH reuse, pH*vL)
        #pragma unroll
        for (int ks = 0; ks < 4; ks++) {
            uint32_t pH[4], pL[4], vH[4][4];
            split2(sacc[2*ks][0],   sacc[2*ks][1],   pH[0], pL[0]);
            split2(sacc[2*ks][2],   sacc[2*ks][3],   pH[1], pL[1]);
            split2(sacc[2*ks+1][0], sacc[2*ks+1][1], pH[2], pL[2]);
            split2(sacc[2*ks+1][2], sacc[2*ks+1][3], pH[3], pL[3]);
            #pragma unroll
            for (int dp = 0; dp < 4; dp++) {
                ldsm4(vH[dp], fraddr(sb + st + 16384, lane, dp * 16, 2 * ks));
                mma_bf16(oacc[2*dp],   pH, vH[dp][0], vH[dp][2]);
                mma_bf16(oacc[2*dp+1], pH, vH[dp][1], vH[dp][3]);
            }
            #pragma unroll
            for (int dp = 0; dp < 4; dp++) {
                mma_bf16(oacc[2*dp],   pL, vH[dp][0], vH[dp][2]);
                mma_bf16(oacc[2*dp+1], pL, vH[dp][1], vH[dp][3]);
            }
            #pragma unroll
            for (int dp = 0; dp < 4; dp++) {
                uint32_t vL[4];
                ldsm4(vL, fraddr(sb + st + 24576, lane, dp * 16, 2 * ks));
                mma_bf16(oacc[2*dp],   pH, vL[0], vL[2]);
                mma_bf16(oacc[2*dp+1], pH, vL[1], vL[3]);
            }
        }
        __syncthreads();
    }

    #pragma unroll
    for (int i = 0; i < 2; i++) {
        lsum[i] += __shfl_xor_sync(0xffffffffu, lsum[i], 1);
        lsum[i] += __shfl_xor_sync(0xffffffffu, lsum[i], 2);
    }
    float inv0 = 1.0f / lsum[0], inv1 = 1.0f / lsum[1];

    #pragma unroll
    for (int np = 0; np < 8; np++)
        #pragma unroll
        for (int h2 = 0; h2 < 2; h2++) {
            int q = q0 + wq + (lane >> 2) + h2 * 8;
            int d = np * 8 + 2 * (lane & 3);
            float inv = h2 ? inv1 : inv0;
            float v0 = oacc[np][h2 * 2] * inv;
            float v1 = oacc[np][h2 * 2 + 1] * inv;
            uint32_t hi, lo;
            split2(v0, v1, hi, lo);
            size_t o = (size_t)(b * SEQ + q) * DM + hd * DH + d;
            *(uint32_t*)(g_zh + o) = hi;
            *(uint32_t*)(g_zl + o) = lo;
        }
}

// ---------------------------------------------------------------------------
extern "C" void kernel_launch(void* const* d_in, const int* in_sizes, int n_in,
                              void* d_out, int out_size)
{
    const float* qin = (const float*)d_in[0];
    const float* kin = (const float*)d_in[1];
    const float* vin = (const float*)d_in[2];
    const float* WQ  = (const float*)d_in[3];
    const float* WK  = (const float*)d_in[4];
    const float* WV  = (const float*)d_in[5];
    const float* WO  = (const float*)d_in[6];
    const float* bQ  = (const float*)d_in[7];
    const float* bK  = (const float*)d_in[8];
    const float* bV  = (const float*)d_in[9];
    const float* bO  = (const float*)d_in[10];
    float* out = (float*)d_out;

    cudaFuncSetAttribute(qkv_proj_mma, cudaFuncAttributeMaxDynamicSharedMemorySize, 131072);
    cudaFuncSetAttribute(out_proj_mma, cudaFuncAttributeMaxDynamicSharedMemorySize, 131072);
    cudaFuncSetAttribute(attn_mma,     cudaFuncAttributeMaxDynamicSharedMemorySize, 98304);

    cvt_x_kernel<<<dim3(MTOT * DM / 8 / 256, 3), 256>>>(qin, kin, vin);
    cvt_wqkv_kernel<<<dim3(32, 2, 48), dim3(32, 8)>>>(WQ, WK, WV);
    cvt_wo_kernel<<<dim3(32, 32), dim3(32, 8)>>>(WO);

    qkv_proj_mma<<<dim3(DM / 128, MTOT / 128, 3), 256, 131072>>>(bQ, bK, bV);
    attn_mma<<<dim3(SEQ / 128, NH, BATCH), 256, 98304>>>();
    out_proj_mma<<<dim3(DM / 128, MTOT / 128), 256, 131072>>>(bO, out);
}

// round 9
// speedup vs baseline: 1.1983x; 1.0634x over previous
#include <cuda_runtime.h>
#include <cuda_bf16.h>
#include <cuda_fp16.h>
#include <stdint.h>

#define BATCH 2
#define SEQ 2048
#define DM 1024
#define NH 16
#define DH 64
#define MTOT (BATCH*SEQ)
#define QSCALE 0.18033688f   // log2(e) / sqrt(64)

typedef __nv_bfloat16 bf16;

// ---------------- device-global scratch ----------------
__device__ __align__(16) bf16 g_xh[3ull*MTOT*DM], g_xl[3ull*MTOT*DM];
__device__ __align__(16) bf16 g_wth[3ull*DM*DM],  g_wtl[3ull*DM*DM];
__device__ __align__(16) bf16 g_woth[(size_t)DM*DM], g_wotl[(size_t)DM*DM];
__device__ __align__(16) bf16 g_qh[(size_t)MTOT*DM], g_ql[(size_t)MTOT*DM];
__device__ __align__(16) bf16 g_kh[(size_t)MTOT*DM], g_kl[(size_t)MTOT*DM];
__device__ __align__(16) __half g_vth[(size_t)MTOT*DM], g_vtl[(size_t)MTOT*DM]; // fp16 [bh*64+d][seq]
__device__ __align__(16) bf16 g_zh[(size_t)MTOT*DM], g_zl[(size_t)MTOT*DM];

// ---------------- helpers ----------------
__device__ __forceinline__ uint32_t smem_u32(const void* p) {
    uint32_t a;
    asm("{ .reg .u64 t; cvta.to.shared.u64 t, %1; cvt.u32.u64 %0, t; }" : "=r"(a) : "l"(p));
    return a;
}
#define SWZ128(o) ((o) ^ (((o) >> 3) & 0x70))

__device__ __forceinline__ void mma_bf16(float* c, const uint32_t* a, uint32_t b0, uint32_t b1) {
    asm volatile("mma.sync.aligned.m16n8k16.row.col.f32.bf16.bf16.f32 "
        "{%0,%1,%2,%3}, {%4,%5,%6,%7}, {%8,%9}, {%0,%1,%2,%3};"
        : "+f"(c[0]), "+f"(c[1]), "+f"(c[2]), "+f"(c[3])
        : "r"(a[0]), "r"(a[1]), "r"(a[2]), "r"(a[3]), "r"(b0), "r"(b1));
}
__device__ __forceinline__ void mma_f16(float* c, const uint32_t* a, uint32_t b0, uint32_t b1) {
    asm volatile("mma.sync.aligned.m16n8k16.row.col.f32.f16.f16.f32 "
        "{%0,%1,%2,%3}, {%4,%5,%6,%7}, {%8,%9}, {%0,%1,%2,%3};"
        : "+f"(c[0]), "+f"(c[1]), "+f"(c[2]), "+f"(c[3])
        : "r"(a[0]), "r"(a[1]), "r"(a[2]), "r"(a[3]), "r"(b0), "r"(b1));
}
__device__ __forceinline__ void ldsm4(uint32_t* r, uint32_t a) {
    asm volatile("ldmatrix.sync.aligned.m8n8.x4.shared.b16 {%0,%1,%2,%3}, [%4];"
        : "=r"(r[0]), "=r"(r[1]), "=r"(r[2]), "=r"(r[3]) : "r"(a));
}
__device__ __forceinline__ uint32_t fraddr(uint32_t base, int lane, int r0, int ku) {
    int g = lane >> 3, r8 = lane & 7;
    return base + SWZ128(((r0 + r8 + ((g & 1) << 3)) << 7) + ((ku + (g >> 1)) << 4));
}
// pack 2 floats into f16x2 (lo -> low half) and exp2 both
__device__ __forceinline__ uint32_t h2exp2(float lo, float hi) {
    uint32_t d;
    asm("cvt.rn.f16x2.f32 %0, %1, %2;" : "=r"(d) : "f"(hi), "f"(lo));
    asm("ex2.approx.f16x2 %0, %0;" : "+r"(d));
    return d;
}
__device__ __forceinline__ uint32_t hadd2(uint32_t a, uint32_t b) {
    uint32_t d;
    asm("add.f16x2 %0, %1, %2;" : "=r"(d) : "r"(a), "r"(b));
    return d;
}
__device__ __forceinline__ void split2(float a, float b, uint32_t& hi, uint32_t& lo) {
    bf16 ah = __float2bfloat16(a), bh = __float2bfloat16(b);
    __nv_bfloat162 H; H.x = ah; H.y = bh;
    __nv_bfloat162 L;
    L.x = __float2bfloat16(a - __bfloat162float(ah));
    L.y = __float2bfloat16(b - __bfloat162float(bh));
    hi = *(uint32_t*)&H; lo = *(uint32_t*)&L;
}
__device__ __forceinline__ void cpa16(uint32_t dst, const void* src) {
    asm volatile("cp.async.cg.shared.global [%0], [%1], 16;" :: "r"(dst), "l"(src) : "memory");
}
#define CP_COMMIT() asm volatile("cp.async.commit_group;" ::: "memory")
#define CP_WAIT(n)  asm volatile("cp.async.wait_group %0;" :: "n"(n) : "memory")

// ---------------- conversion kernels ----------------
__global__ __launch_bounds__(256) void cvt_x_kernel(
    const float* __restrict__ q, const float* __restrict__ k, const float* __restrict__ v) {
    const int z = blockIdx.y;
    const float* __restrict__ src = (z == 0) ? q : (z == 1) ? k : v;
    size_t base = (size_t)z * MTOT * DM;
    size_t i = ((size_t)blockIdx.x * 256 + threadIdx.x) * 8;
    union { bf16 b[8]; uint4 u; } H, L;
    #pragma unroll
    for (int j = 0; j < 8; j += 4) {
        float4 f = *(const float4*)(src + i + j);
        float fv[4] = {f.x, f.y, f.z, f.w};
        #pragma unroll
        for (int q4 = 0; q4 < 4; q4++) {
            bf16 hh = __float2bfloat16(fv[q4]);
            H.b[j + q4] = hh;
            L.b[j + q4] = __float2bfloat16(fv[q4] - __bfloat162float(hh));
        }
    }
    *(uint4*)(g_xh + base + i) = H.u;
    *(uint4*)(g_xl + base + i) = L.u;
}

__global__ __launch_bounds__(256) void cvt_wqkv_kernel(
    const float* __restrict__ wq, const float* __restrict__ wk, const float* __restrict__ wv) {
    __shared__ float s[32][33];
    const int w = blockIdx.z >> 4, hh = blockIdx.z & 15;
    const float* __restrict__ W = ((w == 0) ? wq : (w == 1) ? wk : wv) + (size_t)hh * DM * DH;
    const int k0 = blockIdx.x * 32, e0 = blockIdx.y * 32;
    const int tx = threadIdx.x, ty = threadIdx.y;
    #pragma unroll
    for (int i = 0; i < 4; i++)
        s[ty + 8 * i][tx] = W[(size_t)(k0 + ty + 8 * i) * DH + e0 + tx];
    __syncthreads();
    size_t dbase = (size_t)w * DM * DM;
    #pragma unroll
    for (int i = 0; i < 4; i++) {
        float v = s[tx][ty + 8 * i];
        bf16 hi = __float2bfloat16(v);
        size_t o = dbase + (size_t)(hh * 64 + e0 + ty + 8 * i) * DM + k0 + tx;
        g_wth[o] = hi;
        g_wtl[o] = __float2bfloat16(v - __bfloat162float(hi));
    }
}

__global__ __launch_bounds__(256) void cvt_wo_kernel(const float* __restrict__ W) {
    __shared__ float s[32][33];
    const int k0 = blockIdx.x * 32, d0 = blockIdx.y * 32;
    const int tx = threadIdx.x, ty = threadIdx.y;
    #pragma unroll
    for (int i = 0; i < 4; i++)
        s[ty + 8 * i][tx] = W[(size_t)(k0 + ty + 8 * i) * DM + d0 + tx];
    __syncthreads();
    #pragma unroll
    for (int i = 0; i < 4; i++) {
        float v = s[tx][ty + 8 * i];
        bf16 hi = __float2bfloat16(v);
        size_t o = (size_t)(d0 + ty + 8 * i) * DM + k0 + tx;
        g_woth[o] = hi;
        g_wotl[o] = __float2bfloat16(v - __bfloat162float(hi));
    }
}

// ---------------- split-bf16 GEMM: C[128x128] = X @ Wt^T (+bias) ----------------
#define PJ_STAGE 65536

__device__ __forceinline__ void proj_copy(
    const bf16* __restrict__ Xh, const bf16* __restrict__ Xl,
    const bf16* __restrict__ Wh, const bf16* __restrict__ Wl,
    uint32_t sb, int st, int m0, int n0, int k0, int t)
{
    #pragma unroll
    for (int u = 0; u < 8; u++) {
        int idx = u * 256 + t;
        int sp = idx >> 10, row = (idx >> 3) & 127, c = idx & 7;
        uint32_t so = SWZ128((row << 7) + (c << 4));
        cpa16(sb + st + sp * 16384 + so,
              (sp ? Xl : Xh) + (size_t)(m0 + row) * DM + k0 + c * 8);
        cpa16(sb + st + 32768 + sp * 16384 + so,
              (sp ? Wl : Wh) + (size_t)(n0 + row) * DM + k0 + c * 8);
    }
}

__device__ __forceinline__ void proj_compute(uint32_t sb, int st, int lane,
                                             int wm, int wn, float acc[2][8][4])
{
    #pragma unroll
    for (int ks = 0; ks < 4; ks++) {
        uint32_t aH[2][4], aL[2][4], bH[4][4];
        #pragma unroll
        for (int mt = 0; mt < 2; mt++) {
            ldsm4(aH[mt], fraddr(sb + st,         lane, wm + mt * 16, 2 * ks));
            ldsm4(aL[mt], fraddr(sb + st + 16384, lane, wm + mt * 16, 2 * ks));
        }
        #pragma unroll
        for (int np = 0; np < 4; np++) {              // pass 1: aH * bH
            ldsm4(bH[np], fraddr(sb + st + 32768, lane, wn + np * 16, 2 * ks));
            mma_bf16(acc[0][2*np],   aH[0], bH[np][0], bH[np][2]);
            mma_bf16(acc[0][2*np+1], aH[0], bH[np][1], bH[np][3]);
            mma_bf16(acc[1][2*np],   aH[1], bH[np][0], bH[np][2]);
            mma_bf16(acc[1][2*np+1], aH[1], bH[np][1], bH[np][3]);
        }
        #pragma unroll
        for (int np = 0; np < 4; np++) {              // pass 2: aL * bH
            mma_bf16(acc[0][2*np],   aL[0], bH[np][0], bH[np][2]);
            mma_bf16(acc[0][2*np+1], aL[0], bH[np][1], bH[np][3]);
            mma_bf16(acc[1][2*np],   aL[1], bH[np][0], bH[np][2]);
            mma_bf16(acc[1][2*np+1], aL[1], bH[np][1], bH[np][3]);
        }
        #pragma unroll
        for (int np = 0; np < 4; np++) {              // pass 3: aH * bL
            uint32_t bL[4];
            ldsm4(bL, fraddr(sb + st + 49152, lane, wn + np * 16, 2 * ks));
            mma_bf16(acc[0][2*np],   aH[0], bL[0], bL[2]);
            mma_bf16(acc[0][2*np+1], aH[0], bL[1], bL[3]);
            mma_bf16(acc[1][2*np],   aH[1], bL[0], bL[2]);
            mma_bf16(acc[1][2*np+1], aH[1], bL[1], bL[3]);
        }
    }
}

// mode: 0=Q (scale, split out), 1=K (split out), 2=V (fp16 transposed split out), 3=fp32 out
__device__ __forceinline__ void proj_core(
    const bf16* __restrict__ Xh, const bf16* __restrict__ Xl,
    const bf16* __restrict__ Wh, const bf16* __restrict__ Wl,
    const float* __restrict__ bias,
    bf16* __restrict__ Oh, bf16* __restrict__ Ol, float* __restrict__ Of,
    char* sm, int m0, int n0, int mode)
{
    const int t = threadIdx.x, lane = t & 31, w = t >> 5;
    const uint32_t sb = smem_u32(sm);
    const int wm = (w & 3) * 32, wn = (w >> 2) * 64;
    float acc[2][8][4] = {};

    proj_copy(Xh, Xl, Wh, Wl, sb, 0, m0, n0, 0, t);
    CP_COMMIT();

    for (int kc = 0; kc < 16; kc++) {
        if (kc + 1 < 16) {
            proj_copy(Xh, Xl, Wh, Wl, sb, ((kc + 1) & 1) * PJ_STAGE, m0, n0, (kc + 1) * 64, t);
            CP_COMMIT();
            CP_WAIT(1);
        } else {
            CP_WAIT(0);
        }
        __syncthreads();
        proj_compute(sb, (kc & 1) * PJ_STAGE, lane, wm, wn, acc);
        __syncthreads();
    }

    const float scale = (mode == 0) ? QSCALE : 1.0f;
    #pragma unroll
    for (int mt = 0; mt < 2; mt++)
        #pragma unroll
        for (int np = 0; np < 8; np++)
            #pragma unroll
            for (int h2 = 0; h2 < 2; h2++) {
                int m = m0 + wm + mt * 16 + (lane >> 2) + h2 * 8;
                int n = n0 + wn + np * 8 + 2 * (lane & 3);
                float v0 = (acc[mt][np][h2 * 2]     + bias[n])     * scale;
                float v1 = (acc[mt][np][h2 * 2 + 1] + bias[n + 1]) * scale;
                if (mode == 3) {
                    *(float2*)(Of + (size_t)m * DM + n) = make_float2(v0, v1);
                } else if (mode == 2) {
                    __half* VH = (__half*)Oh;
                    __half* VL = (__half*)Ol;
                    int bb = m >> 11, seq = m & 2047;
                    __half h0 = __float2half_rn(v0), h1 = __float2half_rn(v1);
                    size_t o0 = ((size_t)(bb * NH + (n >> 6)) * DH + (n & 63)) * SEQ + seq;
                    size_t o1 = ((size_t)(bb * NH + ((n+1) >> 6)) * DH + ((n+1) & 63)) * SEQ + seq;
                    VH[o0] = h0; VL[o0] = __float2half_rn(v0 - __half2float(h0));
                    VH[o1] = h1; VL[o1] = __float2half_rn(v1 - __half2float(h1));
                } else {
                    uint32_t hi, lo;
                    split2(v0, v1, hi, lo);
                    *(uint32_t*)(Oh + (size_t)m * DM + n) = hi;
                    *(uint32_t*)(Ol + (size_t)m * DM + n) = lo;
                }
            }
}

__global__ __launch_bounds__(256, 1) void qkv_proj_mma(const float* bq, const float* bk,
                                                       const float* bv) {
    extern __shared__ char sm[];
    const int z = blockIdx.z;
    proj_core(g_xh + (size_t)z * MTOT * DM, g_xl + (size_t)z * MTOT * DM,
              g_wth + (size_t)z * DM * DM, g_wtl + (size_t)z * DM * DM,
              (z == 0) ? bq : (z == 1) ? bk : bv,
              (z == 0) ? g_qh : (z == 1) ? g_kh : (bf16*)g_vth,
              (z == 0) ? g_ql : (z == 1) ? g_kl : (bf16*)g_vtl,
              nullptr, sm, blockIdx.y * 128, blockIdx.x * 128, z);
}

__global__ __launch_bounds__(256, 1) void out_proj_mma(const float* bo, float* out) {
    extern __shared__ char sm[];
    proj_core(g_zh, g_zl, g_woth, g_wotl, bo, nullptr, nullptr, out,
              sm, blockIdx.y * 128, blockIdx.x * 128, 3);
}

// ---------------- FA2 attention: f16 softmax path, 2-stage K/V ----------------
// smem: Q_hi@0 Q_lo@16K; stage s @ 32K+32K*s: K_hi 0, K_lo 8K, V_hi 16K, V_lo 24K. 96KB.
#define AT_ST0 32768
#define AT_SS  32768

__device__ __forceinline__ void attn_copy(uint32_t sb, int kb, int b, int hd, int t) {
    const int st = AT_ST0 + (kb & 1) * AT_SS;
    const int k0 = kb * 64;
    #pragma unroll
    for (int u = 0; u < 4; u++) {
        int idx = u * 256 + t;
        int sp = idx >> 9, row = (idx >> 3) & 63, c = idx & 7;
        uint32_t so = SWZ128((row << 7) + (c << 4));
        cpa16(sb + st + sp * 8192 + so,
              (sp ? g_kl : g_kh) + (size_t)(b * SEQ + k0 + row) * DM + hd * DH + c * 8);
        cpa16(sb + st + 16384 + sp * 8192 + so,
              (sp ? g_vtl : g_vth) + ((size_t)((b * NH + hd) * DH + row)) * SEQ + k0 + c * 8);
    }
}

__global__ __launch_bounds__(256, 1) void attn_mma() {
    extern __shared__ char sm[];
    const uint32_t sb = smem_u32(sm);
    const int t = threadIdx.x, lane = t & 31, w = t >> 5;
    const int qb = (gridDim.x - 1) - blockIdx.x;    // largest-first
    const int hd = blockIdx.y, b = blockIdx.z;
    const int q0 = qb * 128, wq = w * 16;
    const int nkb = 2 * qb + 2;

    attn_copy(sb, 0, b, hd, t);
    CP_COMMIT();

    // Q tile (128 x 64, hi/lo), plain stores
    {
        int r = t >> 1, s = t & 1;
        const bf16* __restrict__ src =
            (s ? g_ql : g_qh) + (size_t)(b * SEQ + q0 + r) * DM + hd * DH;
        char* dst = sm + (s ? 16384 : 0);
        #pragma unroll
        for (int i = 0; i < 8; i++)
            *(uint4*)(dst + SWZ128((r << 7) + (i << 4))) = *(const uint4*)(src + i * 8);
    }
    __syncthreads();

    uint32_t qH[4][4], qL[4][4];
    #pragma unroll
    for (int ks = 0; ks < 4; ks++) {
        ldsm4(qH[ks], fraddr(sb,         lane, wq, 2 * ks));
        ldsm4(qL[ks], fraddr(sb + 16384, lane, wq, 2 * ks));
    }

    float oacc[8][4] = {};
    float lsum[2] = {0.0f, 0.0f};

    for (int kb = 0; kb < nkb; kb++) {
        const int k0 = kb * 64;
        const int st = AT_ST0 + (kb & 1) * AT_SS;
        if (kb + 1 < nkb) {
            attn_copy(sb, kb + 1, b, hd, t);
            CP_COMMIT();
            CP_WAIT(1);
        } else {
            CP_WAIT(0);
        }
        __syncthreads();

        // S = Q K^T: term passes (qH*kH, qL*kH reuse, qH*kL)
        float sacc[8][4] = {};
        #pragma unroll
        for (int ds = 0; ds < 4; ds++) {
            uint32_t kH[4][4];
            #pragma unroll
            for (int np = 0; np < 4; np++) {
                ldsm4(kH[np], fraddr(sb + st, lane, np * 16, 2 * ds));
                mma_bf16(sacc[2*np],   qH[ds], kH[np][0], kH[np][2]);
                mma_bf16(sacc[2*np+1], qH[ds], kH[np][1], kH[np][3]);
            }
            #pragma unroll
            for (int np = 0; np < 4; np++) {
                mma_bf16(sacc[2*np],   qL[ds], kH[np][0], kH[np][2]);
                mma_bf16(sacc[2*np+1], qL[ds], kH[np][1], kH[np][3]);
            }
            #pragma unroll
            for (int np = 0; np < 4; np++) {
                uint32_t kL[4];
                ldsm4(kL, fraddr(sb + st + 8192, lane, np * 16, 2 * ds));
                mma_bf16(sacc[2*np],   qH[ds], kL[0], kL[2]);
                mma_bf16(sacc[2*np+1], qH[ds], kL[1], kL[3]);
            }
        }

        // causal mask (diagonal tiles only): force exp2 -> 0
        if (kb >= 2 * qb) {
            #pragma unroll
            for (int np = 0; np < 8; np++)
                #pragma unroll
                for (int j = 0; j < 4; j++) {
                    int kg = k0 + np * 8 + 2 * (lane & 3) + (j & 1);
                    int qg = q0 + wq + (lane >> 2) + (j >> 1) * 8;
                    if (kg > qg) sacc[np][j] = -30000.0f;
                }
        }

        // pack f32 pairs -> f16x2, exp2 both halves; accumulate l in f16x2
        uint32_t pe[8][2];
        uint32_t la0 = 0, la1 = 0;
        #pragma unroll
        for (int np = 0; np < 8; np++) {
            pe[np][0] = h2exp2(sacc[np][0], sacc[np][1]);   // row r
            pe[np][1] = h2exp2(sacc[np][2], sacc[np][3]);   // row r+8
            la0 = hadd2(la0, pe[np][0]);
            la1 = hadd2(la1, pe[np][1]);
        }
        {
            float2 f0 = __half22float2(*reinterpret_cast<__half2*>(&la0));
            float2 f1 = __half22float2(*reinterpret_cast<__half2*>(&la1));
            lsum[0] += f0.x + f0.y;
            lsum[1] += f1.x + f1.y;
        }

        // PV: P fp16 (A-frag = pe), V fp16 hi/lo (2 term passes)
        #pragma unroll
        for (int ks = 0; ks < 4; ks++) {
            uint32_t pf[4] = { pe[2*ks][0], pe[2*ks][1], pe[2*ks+1][0], pe[2*ks+1][1] };
            uint32_t vH[4][4];
            #pragma unroll
            for (int dp = 0; dp < 4; dp++) {
                ldsm4(vH[dp], fraddr(sb + st + 16384, lane, dp * 16, 2 * ks));
                mma_f16(oacc[2*dp],   pf, vH[dp][0], vH[dp][2]);
                mma_f16(oacc[2*dp+1], pf, vH[dp][1], vH[dp][3]);
            }
            #pragma unroll
            for (int dp = 0; dp < 4; dp++) {
                uint32_t vL[4];
                ldsm4(vL, fraddr(sb + st + 24576, lane, dp * 16, 2 * ks));
                mma_f16(oacc[2*dp],   pf, vL[0], vL[2]);
                mma_f16(oacc[2*dp+1], pf, vL[1], vL[3]);
            }
        }
        __syncthreads();
    }

    #pragma unroll
    for (int i = 0; i < 2; i++) {
        lsum[i] += __shfl_xor_sync(0xffffffffu, lsum[i], 1);
        lsum[i] += __shfl_xor_sync(0xffffffffu, lsum[i], 2);
    }
    float inv0 = 1.0f / lsum[0], inv1 = 1.0f / lsum[1];

    #pragma unroll
    for (int np = 0; np < 8; np++)
        #pragma unroll
        for (int h2 = 0; h2 < 2; h2++) {
            int q = q0 + wq + (lane >> 2) + h2 * 8;
            int d = np * 8 + 2 * (lane & 3);
            float inv = h2 ? inv1 : inv0;
            float v0 = oacc[np][h2 * 2] * inv;
            float v1 = oacc[np][h2 * 2 + 1] * inv;
            uint32_t hi, lo;
            split2(v0, v1, hi, lo);
            size_t o = (size_t)(b * SEQ + q) * DM + hd * DH + d;
            *(uint32_t*)(g_zh + o) = hi;
            *(uint32_t*)(g_zl + o) = lo;
        }
}

// ---------------------------------------------------------------------------
extern "C" void kernel_launch(void* const* d_in, const int* in_sizes, int n_in,
                              void* d_out, int out_size)
{
    const float* qin = (const float*)d_in[0];
    const float* kin = (const float*)d_in[1];
    const float* vin = (const float*)d_in[2];
    const float* WQ  = (const float*)d_in[3];
    const float* WK  = (const float*)d_in[4];
    const float* WV  = (const float*)d_in[5];
    const float* WO  = (const float*)d_in[6];
    const float* bQ  = (const float*)d_in[7];
    const float* bK  = (const float*)d_in[8];
    const float* bV  = (const float*)d_in[9];
    const float* bO  = (const float*)d_in[10];
    float* out = (float*)d_out;

    cudaFuncSetAttribute(qkv_proj_mma, cudaFuncAttributeMaxDynamicSharedMemorySize, 131072);
    cudaFuncSetAttribute(out_proj_mma, cudaFuncAttributeMaxDynamicSharedMemorySize, 131072);
    cudaFuncSetAttribute(attn_mma,     cudaFuncAttributeMaxDynamicSharedMemorySize, 98304);

    cvt_x_kernel<<<dim3(MTOT * DM / 8 / 256, 3), 256>>>(qin, kin, vin);
    cvt_wqkv_kernel<<<dim3(32, 2, 48), dim3(32, 8)>>>(WQ, WK, WV);
    cvt_wo_kernel<<<dim3(32, 32), dim3(32, 8)>>>(WO);

    qkv_proj_mma<<<dim3(DM / 128, MTOT / 128, 3), 256, 131072>>>(bQ, bK, bV);
    attn_mma<<<dim3(SEQ / 128, NH, BATCH), 256, 98304>>>();
    out_proj_mma<<<dim3(DM / 128, MTOT / 128), 256, 131072>>>(bO, out);
}

// round 10
// speedup vs baseline: 1.7053x; 1.4231x over previous
#include <cuda_runtime.h>
#include <cuda_bf16.h>
#include <cuda_fp16.h>
#include <stdint.h>

#define BATCH 2
#define SEQ 2048
#define DM 1024
#define NH 16
#define DH 64
#define MTOT (BATCH*SEQ)
#define QSCALE 0.18033688f   // log2(e) / sqrt(64)

// ---------------- device-global scratch (all fp16) ----------------
__device__ __align__(16) __half g_xh[3ull*MTOT*DM], g_xl[3ull*MTOT*DM];
__device__ __align__(16) __half g_wth[3ull*DM*DM];           // W_{q,k,v} transposed, hi only
__device__ __align__(16) __half g_woth[(size_t)DM*DM];       // W_o transposed, hi only
__device__ __align__(16) __half g_qh[(size_t)MTOT*DM], g_ql[(size_t)MTOT*DM];
__device__ __align__(16) __half g_kh[(size_t)MTOT*DM];       // K single fp16
__device__ __align__(16) __half g_vth[(size_t)MTOT*DM];      // V single fp16, [bh*64+d][seq]
__device__ __align__(16) __half g_zh[(size_t)MTOT*DM], g_zl[(size_t)MTOT*DM];

// ---------------- helpers ----------------
__device__ __forceinline__ uint32_t smem_u32(const void* p) {
    uint32_t a;
    asm("{ .reg .u64 t; cvta.to.shared.u64 t, %1; cvt.u32.u64 %0, t; }" : "=r"(a) : "l"(p));
    return a;
}
#define SWZ128(o) ((o) ^ (((o) >> 3) & 0x70))

__device__ __forceinline__ void mma_f16(float* c, const uint32_t* a, uint32_t b0, uint32_t b1) {
    asm volatile("mma.sync.aligned.m16n8k16.row.col.f32.f16.f16.f32 "
        "{%0,%1,%2,%3}, {%4,%5,%6,%7}, {%8,%9}, {%0,%1,%2,%3};"
        : "+f"(c[0]), "+f"(c[1]), "+f"(c[2]), "+f"(c[3])
        : "r"(a[0]), "r"(a[1]), "r"(a[2]), "r"(a[3]), "r"(b0), "r"(b1));
}
__device__ __forceinline__ void ldsm4(uint32_t* r, uint32_t a) {
    asm volatile("ldmatrix.sync.aligned.m8n8.x4.shared.b16 {%0,%1,%2,%3}, [%4];"
        : "=r"(r[0]), "=r"(r[1]), "=r"(r[2]), "=r"(r[3]) : "r"(a));
}
__device__ __forceinline__ uint32_t fraddr(uint32_t base, int lane, int r0, int ku) {
    int g = lane >> 3, r8 = lane & 7;
    return base + SWZ128(((r0 + r8 + ((g & 1) << 3)) << 7) + ((ku + (g >> 1)) << 4));
}
// pack 2 floats into f16x2 (first arg -> low half) and exp2 both
__device__ __forceinline__ uint32_t h2exp2(float lo, float hi) {
    uint32_t d;
    asm("cvt.rn.f16x2.f32 %0, %1, %2;" : "=r"(d) : "f"(hi), "f"(lo));
    asm("ex2.approx.f16x2 %0, %0;" : "+r"(d));
    return d;
}
__device__ __forceinline__ uint32_t hadd2(uint32_t a, uint32_t b) {
    uint32_t d;
    asm("add.f16x2 %0, %1, %2;" : "=r"(d) : "r"(a), "r"(b));
    return d;
}
// fp16 hi/lo split of a float pair
__device__ __forceinline__ void split2h(float a, float b, uint32_t& hi, uint32_t& lo) {
    __half2 H = __floats2half2_rn(a, b);
    float2 hf = __half22float2(H);
    __half2 L = __floats2half2_rn(a - hf.x, b - hf.y);
    hi = *(uint32_t*)&H; lo = *(uint32_t*)&L;
}
__device__ __forceinline__ void cpa16(uint32_t dst, const void* src) {
    asm volatile("cp.async.cg.shared.global [%0], [%1], 16;" :: "r"(dst), "l"(src) : "memory");
}
#define CP_COMMIT() asm volatile("cp.async.commit_group;" ::: "memory")
#define CP_WAIT(n)  asm volatile("cp.async.wait_group %0;" :: "n"(n) : "memory")

// ---------------- conversion kernels ----------------
__global__ __launch_bounds__(256) void cvt_x_kernel(
    const float* __restrict__ q, const float* __restrict__ k, const float* __restrict__ v) {
    const int z = blockIdx.y;
    const float* __restrict__ src = (z == 0) ? q : (z == 1) ? k : v;
    size_t base = (size_t)z * MTOT * DM;
    size_t i = ((size_t)blockIdx.x * 256 + threadIdx.x) * 8;
    union { __half b[8]; uint4 u; } H, L;
    #pragma unroll
    for (int j = 0; j < 8; j += 4) {
        float4 f = *(const float4*)(src + i + j);
        float fv[4] = {f.x, f.y, f.z, f.w};
        #pragma unroll
        for (int q4 = 0; q4 < 4; q4++) {
            __half hh = __float2half_rn(fv[q4]);
            H.b[j + q4] = hh;
            L.b[j + q4] = __float2half_rn(fv[q4] - __half2float(hh));
        }
    }
    *(uint4*)(g_xh + base + i) = H.u;
    *(uint4*)(g_xl + base + i) = L.u;
}

// W[w][h][k][e] -> g_wth[w][(h*64+e)][k]  (fp16 hi only)
__global__ __launch_bounds__(256) void cvt_wqkv_kernel(
    const float* __restrict__ wq, const float* __restrict__ wk, const float* __restrict__ wv) {
    __shared__ float s[32][33];
    const int w = blockIdx.z >> 4, hh = blockIdx.z & 15;
    const float* __restrict__ W = ((w == 0) ? wq : (w == 1) ? wk : wv) + (size_t)hh * DM * DH;
    const int k0 = blockIdx.x * 32, e0 = blockIdx.y * 32;
    const int tx = threadIdx.x, ty = threadIdx.y;
    #pragma unroll
    for (int i = 0; i < 4; i++)
        s[ty + 8 * i][tx] = W[(size_t)(k0 + ty + 8 * i) * DH + e0 + tx];
    __syncthreads();
    size_t dbase = (size_t)w * DM * DM;
    #pragma unroll
    for (int i = 0; i < 4; i++) {
        float v = s[tx][ty + 8 * i];
        size_t o = dbase + (size_t)(hh * 64 + e0 + ty + 8 * i) * DM + k0 + tx;
        g_wth[o] = __float2half_rn(v);
    }
}

// WO[k][d] -> g_woth[d][k] (fp16 hi only)
__global__ __launch_bounds__(256) void cvt_wo_kernel(const float* __restrict__ W) {
    __shared__ float s[32][33];
    const int k0 = blockIdx.x * 32, d0 = blockIdx.y * 32;
    const int tx = threadIdx.x, ty = threadIdx.y;
    #pragma unroll
    for (int i = 0; i < 4; i++)
        s[ty + 8 * i][tx] = W[(size_t)(k0 + ty + 8 * i) * DM + d0 + tx];
    __syncthreads();
    #pragma unroll
    for (int i = 0; i < 4; i++) {
        float v = s[tx][ty + 8 * i];
        size_t o = (size_t)(d0 + ty + 8 * i) * DM + k0 + tx;
        g_woth[o] = __float2half_rn(v);
    }
}

// ---------------- fp16 2-term GEMM: C[128x128] = (Xh+Xl) @ Wh^T (+bias) ----------------
// 256 threads (8 warps: 4M x 2N; warp tile 32m x 64n). K-chunk 64.
// Stage 48KB: A_hi@0 A_lo@16K B_hi@32K. 2 stages = 96KB dynamic.
#define PJ_STAGE 49152

__device__ __forceinline__ void proj_copy(
    const __half* __restrict__ Xh, const __half* __restrict__ Xl,
    const __half* __restrict__ Wh,
    uint32_t sb, int st, int m0, int n0, int k0, int t)
{
    #pragma unroll
    for (int u = 0; u < 8; u++) {                    // A: hi+lo, 2048 segs
        int idx = u * 256 + t;
        int sp = idx >> 10, row = (idx >> 3) & 127, c = idx & 7;
        cpa16(sb + st + sp * 16384 + SWZ128((row << 7) + (c << 4)),
              (sp ? Xl : Xh) + (size_t)(m0 + row) * DM + k0 + c * 8);
    }
    #pragma unroll
    for (int u = 0; u < 4; u++) {                    // B: hi only, 1024 segs
        int idx = u * 256 + t;
        int row = (idx >> 3) & 127, c = idx & 7;
        cpa16(sb + st + 32768 + SWZ128((row << 7) + (c << 4)),
              Wh + (size_t)(n0 + row) * DM + k0 + c * 8);
    }
}

// 2 term passes: (aH*bH over np) then (aL*bH reusing bH frags)
__device__ __forceinline__ void proj_compute(uint32_t sb, int st, int lane,
                                             int wm, int wn, float acc[2][8][4])
{
    #pragma unroll
    for (int ks = 0; ks < 4; ks++) {
        uint32_t aH[2][4], aL[2][4], bH[4][4];
        #pragma unroll
        for (int mt = 0; mt < 2; mt++) {
            ldsm4(aH[mt], fraddr(sb + st,         lane, wm + mt * 16, 2 * ks));
            ldsm4(aL[mt], fraddr(sb + st + 16384, lane, wm + mt * 16, 2 * ks));
        }
        #pragma unroll
        for (int np = 0; np < 4; np++) {
            ldsm4(bH[np], fraddr(sb + st + 32768, lane, wn + np * 16, 2 * ks));
            mma_f16(acc[0][2*np],   aH[0], bH[np][0], bH[np][2]);
            mma_f16(acc[0][2*np+1], aH[0], bH[np][1], bH[np][3]);
            mma_f16(acc[1][2*np],   aH[1], bH[np][0], bH[np][2]);
            mma_f16(acc[1][2*np+1], aH[1], bH[np][1], bH[np][3]);
        }
        #pragma unroll
        for (int np = 0; np < 4; np++) {
            mma_f16(acc[0][2*np],   aL[0], bH[np][0], bH[np][2]);
            mma_f16(acc[0][2*np+1], aL[0], bH[np][1], bH[np][3]);
            mma_f16(acc[1][2*np],   aL[1], bH[np][0], bH[np][2]);
            mma_f16(acc[1][2*np+1], aL[1], bH[np][1], bH[np][3]);
        }
    }
}

// mode: 0=Q (scale, fp16 split out), 1=K (fp16 single), 2=V (fp16 single transposed), 3=fp32 out
__device__ __forceinline__ void proj_core(
    const __half* __restrict__ Xh, const __half* __restrict__ Xl,
    const __half* __restrict__ Wh,
    const float* __restrict__ bias,
    __half* __restrict__ Oh, __half* __restrict__ Ol, float* __restrict__ Of,
    char* sm, int m0, int n0, int mode)
{
    const int t = threadIdx.x, lane = t & 31, w = t >> 5;
    const uint32_t sb = smem_u32(sm);
    const int wm = (w & 3) * 32, wn = (w >> 2) * 64;
    float acc[2][8][4] = {};

    proj_copy(Xh, Xl, Wh, sb, 0, m0, n0, 0, t);
    CP_COMMIT();

    for (int kc = 0; kc < 16; kc++) {
        if (kc + 1 < 16) {
            proj_copy(Xh, Xl, Wh, sb, ((kc + 1) & 1) * PJ_STAGE, m0, n0, (kc + 1) * 64, t);
            CP_COMMIT();
            CP_WAIT(1);
        } else {
            CP_WAIT(0);
        }
        __syncthreads();
        proj_compute(sb, (kc & 1) * PJ_STAGE, lane, wm, wn, acc);
        __syncthreads();
    }

    const float scale = (mode == 0) ? QSCALE : 1.0f;
    #pragma unroll
    for (int mt = 0; mt < 2; mt++)
        #pragma unroll
        for (int np = 0; np < 8; np++)
            #pragma unroll
            for (int h2 = 0; h2 < 2; h2++) {
                int m = m0 + wm + mt * 16 + (lane >> 2) + h2 * 8;
                int n = n0 + wn + np * 8 + 2 * (lane & 3);
                float v0 = (acc[mt][np][h2 * 2]     + bias[n])     * scale;
                float v1 = (acc[mt][np][h2 * 2 + 1] + bias[n + 1]) * scale;
                if (mode == 3) {
                    *(float2*)(Of + (size_t)m * DM + n) = make_float2(v0, v1);
                } else if (mode == 2) {
                    int bb = m >> 11, seq = m & 2047;
                    size_t o0 = ((size_t)(bb * NH + (n >> 6)) * DH + (n & 63)) * SEQ + seq;
                    size_t o1 = ((size_t)(bb * NH + ((n+1) >> 6)) * DH + ((n+1) & 63)) * SEQ + seq;
                    Oh[o0] = __float2half_rn(v0);
                    Oh[o1] = __float2half_rn(v1);
                } else if (mode == 1) {
                    __half2 hp = __floats2half2_rn(v0, v1);
                    *(uint32_t*)(Oh + (size_t)m * DM + n) = *(uint32_t*)&hp;
                } else {
                    uint32_t hi, lo;
                    split2h(v0, v1, hi, lo);
                    *(uint32_t*)(Oh + (size_t)m * DM + n) = hi;
                    *(uint32_t*)(Ol + (size_t)m * DM + n) = lo;
                }
            }
}

__global__ __launch_bounds__(256, 1) void qkv_proj_mma(const float* bq, const float* bk,
                                                       const float* bv) {
    extern __shared__ char sm[];
    const int z = blockIdx.z;
    proj_core(g_xh + (size_t)z * MTOT * DM, g_xl + (size_t)z * MTOT * DM,
              g_wth + (size_t)z * DM * DM,
              (z == 0) ? bq : (z == 1) ? bk : bv,
              (z == 0) ? g_qh : (z == 1) ? g_kh : g_vth,
              (z == 0) ? g_ql : nullptr,
              nullptr, sm, blockIdx.y * 128, blockIdx.x * 128, z);
}

__global__ __launch_bounds__(256, 1) void out_proj_mma(const float* bo, float* out) {
    extern __shared__ char sm[];
    proj_core(g_zh, g_zl, g_woth, bo, nullptr, nullptr, out,
              sm, blockIdx.y * 128, blockIdx.x * 128, 3);
}

// ---------------- FA2 attention: fp16 everywhere, 2-stage K/V ----------------
// smem: Q_hi@0 Q_lo@16K; stage s @ 32K+16K*s: K_hi 0, V_hi 8K. 64KB total.
#define AT_ST0 32768
#define AT_SS  16384

__device__ __forceinline__ void attn_copy(uint32_t sb, int kb, int b, int hd, int t) {
    const int st = AT_ST0 + (kb & 1) * AT_SS;
    const int k0 = kb * 64;
    #pragma unroll
    for (int u = 0; u < 2; u++) {
        int idx = u * 256 + t;              // 512 segs each for K and V
        int row = idx >> 3, c = idx & 7;
        uint32_t so = SWZ128((row << 7) + (c << 4));
        cpa16(sb + st + so,
              g_kh + (size_t)(b * SEQ + k0 + row) * DM + hd * DH + c * 8);
        cpa16(sb + st + 8192 + so,
              g_vth + ((size_t)((b * NH + hd) * DH + row)) * SEQ + k0 + c * 8);
    }
}

__global__ __launch_bounds__(256, 1) void attn_mma() {
    extern __shared__ char sm[];
    const uint32_t sb = smem_u32(sm);
    const int t = threadIdx.x, lane = t & 31, w = t >> 5;
    const int qb = (gridDim.x - 1) - blockIdx.x;    // largest-first
    const int hd = blockIdx.y, b = blockIdx.z;
    const int q0 = qb * 128, wq = w * 16;
    const int nkb = 2 * qb + 2;

    attn_copy(sb, 0, b, hd, t);
    CP_COMMIT();

    // Q tile (128 x 64, fp16 hi/lo), plain stores
    {
        int r = t >> 1, s = t & 1;
        const __half* __restrict__ src =
            (s ? g_ql : g_qh) + (size_t)(b * SEQ + q0 + r) * DM + hd * DH;
        char* dst = sm + (s ? 16384 : 0);
        #pragma unroll
        for (int i = 0; i < 8; i++)
            *(uint4*)(dst + SWZ128((r << 7) + (i << 4))) = *(const uint4*)(src + i * 8);
    }
    __syncthreads();

    uint32_t qH[4][4], qL[4][4];
    #pragma unroll
    for (int ks = 0; ks < 4; ks++) {
        ldsm4(qH[ks], fraddr(sb,         lane, wq, 2 * ks));
        ldsm4(qL[ks], fraddr(sb + 16384, lane, wq, 2 * ks));
    }

    float oacc[8][4] = {};
    float lsum[2] = {0.0f, 0.0f};

    for (int kb = 0; kb < nkb; kb++) {
        const int k0 = kb * 64;
        const int st = AT_ST0 + (kb & 1) * AT_SS;
        if (kb + 1 < nkb) {
            attn_copy(sb, kb + 1, b, hd, t);
            CP_COMMIT();
            CP_WAIT(1);
        } else {
            CP_WAIT(0);
        }
        __syncthreads();

        // S = (qH + qL) K^T — 2 term passes over single-fp16 K
        float sacc[8][4] = {};
        #pragma unroll
        for (int ds = 0; ds < 4; ds++) {
            uint32_t kH[4][4];
            #pragma unroll
            for (int np = 0; np < 4; np++) {
                ldsm4(kH[np], fraddr(sb + st, lane, np * 16, 2 * ds));
                mma_f16(sacc[2*np],   qH[ds], kH[np][0], kH[np][2]);
                mma_f16(sacc[2*np+1], qH[ds], kH[np][1], kH[np][3]);
            }
            #pragma unroll
            for (int np = 0; np < 4; np++) {
                mma_f16(sacc[2*np],   qL[ds], kH[np][0], kH[np][2]);
                mma_f16(sacc[2*np+1], qL[ds], kH[np][1], kH[np][3]);
            }
        }

        // causal mask (diagonal tiles only)
        if (kb >= 2 * qb) {
            #pragma unroll
            for (int np = 0; np < 8; np++)
                #pragma unroll
                for (int j = 0; j < 4; j++) {
                    int kg = k0 + np * 8 + 2 * (lane & 3) + (j & 1);
                    int qg = q0 + wq + (lane >> 2) + (j >> 1) * 8;
                    if (kg > qg) sacc[np][j] = -30000.0f;
                }
        }

        // f16x2 exp2; accumulate l in f16x2
        uint32_t pe[8][2];
        uint32_t la0 = 0, la1 = 0;
        #pragma unroll
        for (int np = 0; np < 8; np++) {
            pe[np][0] = h2exp2(sacc[np][0], sacc[np][1]);
            pe[np][1] = h2exp2(sacc[np][2], sacc[np][3]);
            la0 = hadd2(la0, pe[np][0]);
            la1 = hadd2(la1, pe[np][1]);
        }
        {
            float2 f0 = __half22float2(*reinterpret_cast<__half2*>(&la0));
            float2 f1 = __half22float2(*reinterpret_cast<__half2*>(&la1));
            lsum[0] += f0.x + f0.y;
            lsum[1] += f1.x + f1.y;
        }

        // PV: P fp16 (A-frag = pe), V single fp16
        #pragma unroll
        for (int ks = 0; ks < 4; ks++) {
            uint32_t pf[4] = { pe[2*ks][0], pe[2*ks][1], pe[2*ks+1][0], pe[2*ks+1][1] };
            #pragma unroll
            for (int dp = 0; dp < 4; dp++) {
                uint32_t vH[4];
                ldsm4(vH, fraddr(sb + st + 8192, lane, dp * 16, 2 * ks));
                mma_f16(oacc[2*dp],   pf, vH[0], vH[2]);
                mma_f16(oacc[2*dp+1], pf, vH[1], vH[3]);
            }
        }
        __syncthreads();
    }

    #pragma unroll
    for (int i = 0; i < 2; i++) {
        lsum[i] += __shfl_xor_sync(0xffffffffu, lsum[i], 1);
        lsum[i] += __shfl_xor_sync(0xffffffffu, lsum[i], 2);
    }
    float inv0 = 1.0f / lsum[0], inv1 = 1.0f / lsum[1];

    // z = O / l, fp16 split, [b*SEQ+q][hd*64+d]
    #pragma unroll
    for (int np = 0; np < 8; np++)
        #pragma unroll
        for (int h2 = 0; h2 < 2; h2++) {
            int q = q0 + wq + (lane >> 2) + h2 * 8;
            int d = np * 8 + 2 * (lane & 3);
            float inv = h2 ? inv1 : inv0;
            float v0 = oacc[np][h2 * 2] * inv;
            float v1 = oacc[np][h2 * 2 + 1] * inv;
            uint32_t hi, lo;
            split2h(v0, v1, hi, lo);
            size_t o = (size_t)(b * SEQ + q) * DM + hd * DH + d;
            *(uint32_t*)(g_zh + o) = hi;
            *(uint32_t*)(g_zl + o) = lo;
        }
}

// ---------------------------------------------------------------------------
extern "C" void kernel_launch(void* const* d_in, const int* in_sizes, int n_in,
                              void* d_out, int out_size)
{
    const float* qin = (const float*)d_in[0];
    const float* kin = (const float*)d_in[1];
    const float* vin = (const float*)d_in[2];
    const float* WQ  = (const float*)d_in[3];
    const float* WK  = (const float*)d_in[4];
    const float* WV  = (const float*)d_in[5];
    const float* WO  = (const float*)d_in[6];
    const float* bQ  = (const float*)d_in[7];
    const float* bK  = (const float*)d_in[8];
    const float* bV  = (const float*)d_in[9];
    const float* bO  = (const float*)d_in[10];
    float* out = (float*)d_out;

    cudaFuncSetAttribute(qkv_proj_mma, cudaFuncAttributeMaxDynamicSharedMemorySize, 98304);
    cudaFuncSetAttribute(out_proj_mma, cudaFuncAttributeMaxDynamicSharedMemorySize, 98304);
    cudaFuncSetAttribute(attn_mma,     cudaFuncAttributeMaxDynamicSharedMemorySize, 65536);

    cvt_x_kernel<<<dim3(MTOT * DM / 8 / 256, 3), 256>>>(qin, kin, vin);
    cvt_wqkv_kernel<<<dim3(32, 2, 48), dim3(32, 8)>>>(WQ, WK, WV);
    cvt_wo_kernel<<<dim3(32, 32), dim3(32, 8)>>>(WO);

    qkv_proj_mma<<<dim3(DM / 128, MTOT / 128, 3), 256, 98304>>>(bQ, bK, bV);
    attn_mma<<<dim3(SEQ / 128, NH, BATCH), 256, 65536>>>();
    out_proj_mma<<<dim3(DM / 128, MTOT / 128), 256, 98304>>>(bO, out);
}

// round 11
// speedup vs baseline: 2.6457x; 1.5515x over previous
#include <cuda_runtime.h>
#include <cuda_bf16.h>
#include <cuda_fp16.h>
#include <stdint.h>

#define BATCH 2
#define SEQ 2048
#define DM 1024
#define NH 16
#define DH 64
#define MTOT (BATCH*SEQ)
#define QSCALE 0.18033688f   // log2(e) / sqrt(64)

// ---------------- device-global scratch (all single fp16) ----------------
__device__ __align__(16) __half g_x[3ull*MTOT*DM];           // q/k/v inputs
__device__ __align__(16) __half g_wt[3ull*DM*DM];            // W_{q,k,v} transposed
__device__ __align__(16) __half g_wot[(size_t)DM*DM];        // W_o transposed
__device__ __align__(16) __half g_q[(size_t)MTOT*DM];
__device__ __align__(16) __half g_k[(size_t)MTOT*DM];
__device__ __align__(16) __half g_vt[(size_t)MTOT*DM];       // [bh*64+d][seq]
__device__ __align__(16) __half g_z[(size_t)MTOT*DM];

// ---------------- helpers ----------------
__device__ __forceinline__ uint32_t smem_u32(const void* p) {
    uint32_t a;
    asm("{ .reg .u64 t; cvta.to.shared.u64 t, %1; cvt.u32.u64 %0, t; }" : "=r"(a) : "l"(p));
    return a;
}
#define SWZ128(o) ((o) ^ (((o) >> 3) & 0x70))

__device__ __forceinline__ void mma_f16(float* c, const uint32_t* a, uint32_t b0, uint32_t b1) {
    asm volatile("mma.sync.aligned.m16n8k16.row.col.f32.f16.f16.f32 "
        "{%0,%1,%2,%3}, {%4,%5,%6,%7}, {%8,%9}, {%0,%1,%2,%3};"
        : "+f"(c[0]), "+f"(c[1]), "+f"(c[2]), "+f"(c[3])
        : "r"(a[0]), "r"(a[1]), "r"(a[2]), "r"(a[3]), "r"(b0), "r"(b1));
}
__device__ __forceinline__ void ldsm4(uint32_t* r, uint32_t a) {
    asm volatile("ldmatrix.sync.aligned.m8n8.x4.shared.b16 {%0,%1,%2,%3}, [%4];"
        : "=r"(r[0]), "=r"(r[1]), "=r"(r[2]), "=r"(r[3]) : "r"(a));
}
__device__ __forceinline__ uint32_t fraddr(uint32_t base, int lane, int r0, int ku) {
    int g = lane >> 3, r8 = lane & 7;
    return base + SWZ128(((r0 + r8 + ((g & 1) << 3)) << 7) + ((ku + (g >> 1)) << 4));
}
// pack 2 floats into f16x2 (first arg -> low half) and exp2 both
__device__ __forceinline__ uint32_t h2exp2(float lo, float hi) {
    uint32_t d;
    asm("cvt.rn.f16x2.f32 %0, %1, %2;" : "=r"(d) : "f"(hi), "f"(lo));
    asm("ex2.approx.f16x2 %0, %0;" : "+r"(d));
    return d;
}
__device__ __forceinline__ uint32_t hadd2(uint32_t a, uint32_t b) {
    uint32_t d;
    asm("add.f16x2 %0, %1, %2;" : "=r"(d) : "r"(a), "r"(b));
    return d;
}
__device__ __forceinline__ void cpa16(uint32_t dst, const void* src) {
    asm volatile("cp.async.cg.shared.global [%0], [%1], 16;" :: "r"(dst), "l"(src) : "memory");
}
#define CP_COMMIT() asm volatile("cp.async.commit_group;" ::: "memory")
#define CP_WAIT(n)  asm volatile("cp.async.wait_group %0;" :: "n"(n) : "memory")

// ---------------- conversion kernels ----------------
__global__ __launch_bounds__(256) void cvt_x_kernel(
    const float* __restrict__ q, const float* __restrict__ k, const float* __restrict__ v) {
    const int z = blockIdx.y;
    const float* __restrict__ src = (z == 0) ? q : (z == 1) ? k : v;
    size_t base = (size_t)z * MTOT * DM;
    size_t i = ((size_t)blockIdx.x * 256 + threadIdx.x) * 8;
    union { __half b[8]; uint4 u; } H;
    #pragma unroll
    for (int j = 0; j < 8; j += 4) {
        float4 f = *(const float4*)(src + i + j);
        H.b[j + 0] = __float2half_rn(f.x);
        H.b[j + 1] = __float2half_rn(f.y);
        H.b[j + 2] = __float2half_rn(f.z);
        H.b[j + 3] = __float2half_rn(f.w);
    }
    *(uint4*)(g_x + base + i) = H.u;
}

// W[w][h][k][e] -> g_wt[w][(h*64+e)][k]
__global__ __launch_bounds__(256) void cvt_wqkv_kernel(
    const float* __restrict__ wq, const float* __restrict__ wk, const float* __restrict__ wv) {
    __shared__ float s[32][33];
    const int w = blockIdx.z >> 4, hh = blockIdx.z & 15;
    const float* __restrict__ W = ((w == 0) ? wq : (w == 1) ? wk : wv) + (size_t)hh * DM * DH;
    const int k0 = blockIdx.x * 32, e0 = blockIdx.y * 32;
    const int tx = threadIdx.x, ty = threadIdx.y;
    #pragma unroll
    for (int i = 0; i < 4; i++)
        s[ty + 8 * i][tx] = W[(size_t)(k0 + ty + 8 * i) * DH + e0 + tx];
    __syncthreads();
    size_t dbase = (size_t)w * DM * DM;
    #pragma unroll
    for (int i = 0; i < 4; i++) {
        size_t o = dbase + (size_t)(hh * 64 + e0 + ty + 8 * i) * DM + k0 + tx;
        g_wt[o] = __float2half_rn(s[tx][ty + 8 * i]);
    }
}

// WO[k][d] -> g_wot[d][k]
__global__ __launch_bounds__(256) void cvt_wo_kernel(const float* __restrict__ W) {
    __shared__ float s[32][33];
    const int k0 = blockIdx.x * 32, d0 = blockIdx.y * 32;
    const int tx = threadIdx.x, ty = threadIdx.y;
    #pragma unroll
    for (int i = 0; i < 4; i++)
        s[ty + 8 * i][tx] = W[(size_t)(k0 + ty + 8 * i) * DM + d0 + tx];
    __syncthreads();
    #pragma unroll
    for (int i = 0; i < 4; i++) {
        size_t o = (size_t)(d0 + ty + 8 * i) * DM + k0 + tx;
        g_wot[o] = __float2half_rn(s[tx][ty + 8 * i]);
    }
}

// ---------------- fp16 1-term GEMM: C[128x128] = X @ W^T (+bias) ----------------
// 256 threads (8 warps: 4M x 2N; warp tile 32m x 64n). K-chunk 64.
// Stage 32KB: A@0 B@16K. 2 stages = 64KB dynamic.
#define PJ_STAGE 32768

__device__ __forceinline__ void proj_copy(
    const __half* __restrict__ X, const __half* __restrict__ W,
    uint32_t sb, int st, int m0, int n0, int k0, int t)
{
    #pragma unroll
    for (int u = 0; u < 4; u++) {
        int idx = u * 256 + t;
        int row = idx >> 3, c = idx & 7;
        uint32_t so = SWZ128((row << 7) + (c << 4));
        cpa16(sb + st + so,         X + (size_t)(m0 + row) * DM + k0 + c * 8);
        cpa16(sb + st + 16384 + so, W + (size_t)(n0 + row) * DM + k0 + c * 8);
    }
}

__device__ __forceinline__ void proj_compute(uint32_t sb, int st, int lane,
                                             int wm, int wn, float acc[2][8][4])
{
    #pragma unroll
    for (int ks = 0; ks < 4; ks++) {
        uint32_t aH[2][4];
        #pragma unroll
        for (int mt = 0; mt < 2; mt++)
            ldsm4(aH[mt], fraddr(sb + st, lane, wm + mt * 16, 2 * ks));
        #pragma unroll
        for (int np = 0; np < 4; np++) {
            uint32_t bH[4];
            ldsm4(bH, fraddr(sb + st + 16384, lane, wn + np * 16, 2 * ks));
            mma_f16(acc[0][2*np],   aH[0], bH[0], bH[2]);
            mma_f16(acc[0][2*np+1], aH[0], bH[1], bH[3]);
            mma_f16(acc[1][2*np],   aH[1], bH[0], bH[2]);
            mma_f16(acc[1][2*np+1], aH[1], bH[1], bH[3]);
        }
    }
}

// mode: 0=Q (scale, fp16), 1=K (fp16), 2=V (fp16 transposed), 3=fp32 out
__device__ __forceinline__ void proj_core(
    const __half* __restrict__ X, const __half* __restrict__ W,
    const float* __restrict__ bias,
    __half* __restrict__ Oh, float* __restrict__ Of,
    char* sm, int m0, int n0, int mode)
{
    const int t = threadIdx.x, lane = t & 31, w = t >> 5;
    const uint32_t sb = smem_u32(sm);
    const int wm = (w & 3) * 32, wn = (w >> 2) * 64;
    float acc[2][8][4] = {};

    proj_copy(X, W, sb, 0, m0, n0, 0, t);
    CP_COMMIT();

    for (int kc = 0; kc < 16; kc++) {
        if (kc + 1 < 16) {
            proj_copy(X, W, sb, ((kc + 1) & 1) * PJ_STAGE, m0, n0, (kc + 1) * 64, t);
            CP_COMMIT();
            CP_WAIT(1);
        } else {
            CP_WAIT(0);
        }
        __syncthreads();
        proj_compute(sb, (kc & 1) * PJ_STAGE, lane, wm, wn, acc);
        __syncthreads();
    }

    const float scale = (mode == 0) ? QSCALE : 1.0f;
    #pragma unroll
    for (int mt = 0; mt < 2; mt++)
        #pragma unroll
        for (int np = 0; np < 8; np++)
            #pragma unroll
            for (int h2 = 0; h2 < 2; h2++) {
                int m = m0 + wm + mt * 16 + (lane >> 2) + h2 * 8;
                int n = n0 + wn + np * 8 + 2 * (lane & 3);
                float v0 = (acc[mt][np][h2 * 2]     + bias[n])     * scale;
                float v1 = (acc[mt][np][h2 * 2 + 1] + bias[n + 1]) * scale;
                if (mode == 3) {
                    *(float2*)(Of + (size_t)m * DM + n) = make_float2(v0, v1);
                } else if (mode == 2) {
                    int bb = m >> 11, seq = m & 2047;
                    size_t o0 = ((size_t)(bb * NH + (n >> 6)) * DH + (n & 63)) * SEQ + seq;
                    size_t o1 = ((size_t)(bb * NH + ((n+1) >> 6)) * DH + ((n+1) & 63)) * SEQ + seq;
                    Oh[o0] = __float2half_rn(v0);
                    Oh[o1] = __float2half_rn(v1);
                } else {
                    __half2 hp = __floats2half2_rn(v0, v1);
                    *(uint32_t*)(Oh + (size_t)m * DM + n) = *(uint32_t*)&hp;
                }
            }
}

__global__ __launch_bounds__(256, 1) void qkv_proj_mma(const float* bq, const float* bk,
                                                       const float* bv) {
    extern __shared__ char sm[];
    const int z = blockIdx.z;
    proj_core(g_x + (size_t)z * MTOT * DM, g_wt + (size_t)z * DM * DM,
              (z == 0) ? bq : (z == 1) ? bk : bv,
              (z == 0) ? g_q : (z == 1) ? g_k : g_vt,
              nullptr, sm, blockIdx.y * 128, blockIdx.x * 128, z);
}

__global__ __launch_bounds__(256, 1) void out_proj_mma(const float* bo, float* out) {
    extern __shared__ char sm[];
    proj_core(g_z, g_wot, bo, nullptr, out,
              sm, blockIdx.y * 128, blockIdx.x * 128, 3);
}

// ---------------- FA2 attention: single fp16, 2-stage K/V ----------------
// smem: Q@0 (16K); stage s @ 16K+16K*s: K 0, V 8K. 48KB total.
#define AT_ST0 16384
#define AT_SS  16384

__device__ __forceinline__ void attn_copy(uint32_t sb, int kb, int b, int hd, int t) {
    const int st = AT_ST0 + (kb & 1) * AT_SS;
    const int k0 = kb * 64;
    #pragma unroll
    for (int u = 0; u < 2; u++) {
        int idx = u * 256 + t;
        int row = idx >> 3, c = idx & 7;
        uint32_t so = SWZ128((row << 7) + (c << 4));
        cpa16(sb + st + so,
              g_k + (size_t)(b * SEQ + k0 + row) * DM + hd * DH + c * 8);
        cpa16(sb + st + 8192 + so,
              g_vt + ((size_t)((b * NH + hd) * DH + row)) * SEQ + k0 + c * 8);
    }
}

__global__ __launch_bounds__(256, 1) void attn_mma() {
    extern __shared__ char sm[];
    const uint32_t sb = smem_u32(sm);
    const int t = threadIdx.x, lane = t & 31, w = t >> 5;
    const int qb = (gridDim.x - 1) - blockIdx.x;    // largest-first
    const int hd = blockIdx.y, b = blockIdx.z;
    const int q0 = qb * 128, wq = w * 16;
    const int nkb = 2 * qb + 2;

    attn_copy(sb, 0, b, hd, t);
    CP_COMMIT();

    // Q tile (128 x 64 fp16), plain stores (each thread: half a row)
    {
        int r = t >> 1, half = t & 1;
        const __half* __restrict__ src =
            g_q + (size_t)(b * SEQ + q0 + r) * DM + hd * DH + half * 32;
        #pragma unroll
        for (int i = 0; i < 4; i++)
            *(uint4*)(sm + SWZ128((r << 7) + ((half * 4 + i) << 4))) =
                *(const uint4*)(src + i * 8);
    }
    __syncthreads();

    uint32_t qH[4][4];
    #pragma unroll
    for (int ks = 0; ks < 4; ks++)
        ldsm4(qH[ks], fraddr(sb, lane, wq, 2 * ks));

    float oacc[8][4] = {};
    float lsum[2] = {0.0f, 0.0f};

    for (int kb = 0; kb < nkb; kb++) {
        const int k0 = kb * 64;
        const int st = AT_ST0 + (kb & 1) * AT_SS;
        if (kb + 1 < nkb) {
            attn_copy(sb, kb + 1, b, hd, t);
            CP_COMMIT();
            CP_WAIT(1);
        } else {
            CP_WAIT(0);
        }
        __syncthreads();

        // S = Q K^T (1 term)
        float sacc[8][4] = {};
        #pragma unroll
        for (int ds = 0; ds < 4; ds++)
            #pragma unroll
            for (int np = 0; np < 4; np++) {
                uint32_t kH[4];
                ldsm4(kH, fraddr(sb + st, lane, np * 16, 2 * ds));
                mma_f16(sacc[2*np],   qH[ds], kH[0], kH[2]);
                mma_f16(sacc[2*np+1], qH[ds], kH[1], kH[3]);
            }

        // causal mask (diagonal tiles only)
        if (kb >= 2 * qb) {
            #pragma unroll
            for (int np = 0; np < 8; np++)
                #pragma unroll
                for (int j = 0; j < 4; j++) {
                    int kg = k0 + np * 8 + 2 * (lane & 3) + (j & 1);
                    int qg = q0 + wq + (lane >> 2) + (j >> 1) * 8;
                    if (kg > qg) sacc[np][j] = -30000.0f;
                }
        }

        // f16x2 exp2; accumulate l in f16x2
        uint32_t pe[8][2];
        uint32_t la0 = 0, la1 = 0;
        #pragma unroll
        for (int np = 0; np < 8; np++) {
            pe[np][0] = h2exp2(sacc[np][0], sacc[np][1]);
            pe[np][1] = h2exp2(sacc[np][2], sacc[np][3]);
            la0 = hadd2(la0, pe[np][0]);
            la1 = hadd2(la1, pe[np][1]);
        }
        {
            float2 f0 = __half22float2(*reinterpret_cast<__half2*>(&la0));
            float2 f1 = __half22float2(*reinterpret_cast<__half2*>(&la1));
            lsum[0] += f0.x + f0.y;
            lsum[1] += f1.x + f1.y;
        }

        // PV: P fp16 (A-frag = pe), V single fp16
        #pragma unroll
        for (int ks = 0; ks < 4; ks++) {
            uint32_t pf[4] = { pe[2*ks][0], pe[2*ks][1], pe[2*ks+1][0], pe[2*ks+1][1] };
            #pragma unroll
            for (int dp = 0; dp < 4; dp++) {
                uint32_t vH[4];
                ldsm4(vH, fraddr(sb + st + 8192, lane, dp * 16, 2 * ks));
                mma_f16(oacc[2*dp],   pf, vH[0], vH[2]);
                mma_f16(oacc[2*dp+1], pf, vH[1], vH[3]);
            }
        }
        __syncthreads();
    }

    #pragma unroll
    for (int i = 0; i < 2; i++) {
        lsum[i] += __shfl_xor_sync(0xffffffffu, lsum[i], 1);
        lsum[i] += __shfl_xor_sync(0xffffffffu, lsum[i], 2);
    }
    float inv0 = 1.0f / lsum[0], inv1 = 1.0f / lsum[1];

    // z = O / l, single fp16, [b*SEQ+q][hd*64+d]
    #pragma unroll
    for (int np = 0; np < 8; np++)
        #pragma unroll
        for (int h2 = 0; h2 < 2; h2++) {
            int q = q0 + wq + (lane >> 2) + h2 * 8;
            int d = np * 8 + 2 * (lane & 3);
            float inv = h2 ? inv1 : inv0;
            __half2 hp = __floats2half2_rn(oacc[np][h2 * 2] * inv,
                                           oacc[np][h2 * 2 + 1] * inv);
            size_t o = (size_t)(b * SEQ + q) * DM + hd * DH + d;
            *(uint32_t*)(g_z + o) = *(uint32_t*)&hp;
        }
}

// ---------------------------------------------------------------------------
extern "C" void kernel_launch(void* const* d_in, const int* in_sizes, int n_in,
                              void* d_out, int out_size)
{
    const float* qin = (const float*)d_in[0];
    const float* kin = (const float*)d_in[1];
    const float* vin = (const float*)d_in[2];
    const float* WQ  = (const float*)d_in[3];
    const float* WK  = (const float*)d_in[4];
    const float* WV  = (const float*)d_in[5];
    const float* WO  = (const float*)d_in[6];
    const float* bQ  = (const float*)d_in[7];
    const float* bK  = (const float*)d_in[8];
    const float* bV  = (const float*)d_in[9];
    const float* bO  = (const float*)d_in[10];
    float* out = (float*)d_out;

    cudaFuncSetAttribute(qkv_proj_mma, cudaFuncAttributeMaxDynamicSharedMemorySize, 65536);
    cudaFuncSetAttribute(out_proj_mma, cudaFuncAttributeMaxDynamicSharedMemorySize, 65536);
    cudaFuncSetAttribute(attn_mma,     cudaFuncAttributeMaxDynamicSharedMemorySize, 49152);

    cvt_x_kernel<<<dim3(MTOT * DM / 8 / 256, 3), 256>>>(qin, kin, vin);
    cvt_wqkv_kernel<<<dim3(32, 2, 48), dim3(32, 8)>>>(WQ, WK, WV);
    cvt_wo_kernel<<<dim3(32, 32), dim3(32, 8)>>>(WO);

    qkv_proj_mma<<<dim3(DM / 128, MTOT / 128, 3), 256, 65536>>>(bQ, bK, bV);
    attn_mma<<<dim3(SEQ / 128, NH, BATCH), 256, 49152>>>();
    out_proj_mma<<<dim3(DM / 128, MTOT / 128), 256, 65536>>>(bO, out);
}

// round 12
// speedup vs baseline: 2.9188x; 1.1032x over previous
#include <cuda_runtime.h>
#include <cuda_bf16.h>
#include <cuda_fp16.h>
#include <stdint.h>

#define BATCH 2
#define SEQ 2048
#define DM 1024
#define NH 16
#define DH 64
#define MTOT (BATCH*SEQ)
#define QSCALE 0.18033688f   // log2(e) / sqrt(64)

// ---------------- device-global scratch (all single fp16) ----------------
__device__ __align__(16) __half g_x[3ull*MTOT*DM];           // q/k/v inputs
__device__ __align__(16) __half g_wt[3ull*DM*DM];            // W_{q,k,v} transposed
__device__ __align__(16) __half g_wot[(size_t)DM*DM];        // W_o transposed
__device__ __align__(16) __half g_q[(size_t)MTOT*DM];
__device__ __align__(16) __half g_k[(size_t)MTOT*DM];
__device__ __align__(16) __half g_vt[(size_t)MTOT*DM];       // [bh*64+d][seq]
__device__ __align__(16) __half g_z[(size_t)MTOT*DM];

// ---------------- helpers ----------------
__device__ __forceinline__ uint32_t smem_u32(const void* p) {
    uint32_t a;
    asm("{ .reg .u64 t; cvta.to.shared.u64 t, %1; cvt.u32.u64 %0, t; }" : "=r"(a) : "l"(p));
    return a;
}
#define SWZ128(o) ((o) ^ (((o) >> 3) & 0x70))

__device__ __forceinline__ void mma_f16(float* c, const uint32_t* a, uint32_t b0, uint32_t b1) {
    asm volatile("mma.sync.aligned.m16n8k16.row.col.f32.f16.f16.f32 "
        "{%0,%1,%2,%3}, {%4,%5,%6,%7}, {%8,%9}, {%0,%1,%2,%3};"
        : "+f"(c[0]), "+f"(c[1]), "+f"(c[2]), "+f"(c[3])
        : "r"(a[0]), "r"(a[1]), "r"(a[2]), "r"(a[3]), "r"(b0), "r"(b1));
}
__device__ __forceinline__ void ldsm4(uint32_t* r, uint32_t a) {
    asm volatile("ldmatrix.sync.aligned.m8n8.x4.shared.b16 {%0,%1,%2,%3}, [%4];"
        : "=r"(r[0]), "=r"(r[1]), "=r"(r[2]), "=r"(r[3]) : "r"(a));
}
__device__ __forceinline__ uint32_t fraddr(uint32_t base, int lane, int r0, int ku) {
    int g = lane >> 3, r8 = lane & 7;
    return base + SWZ128(((r0 + r8 + ((g & 1) << 3)) << 7) + ((ku + (g >> 1)) << 4));
}
// pack 2 floats into f16x2 (first arg -> low half) and exp2 both
__device__ __forceinline__ uint32_t h2exp2(float lo, float hi) {
    uint32_t d;
    asm("cvt.rn.f16x2.f32 %0, %1, %2;" : "=r"(d) : "f"(hi), "f"(lo));
    asm("ex2.approx.f16x2 %0, %0;" : "+r"(d));
    return d;
}
__device__ __forceinline__ uint32_t hadd2(uint32_t a, uint32_t b) {
    uint32_t d;
    asm("add.f16x2 %0, %1, %2;" : "=r"(d) : "r"(a), "r"(b));
    return d;
}
__device__ __forceinline__ void cpa16(uint32_t dst, const void* src) {
    asm volatile("cp.async.cg.shared.global [%0], [%1], 16;" :: "r"(dst), "l"(src) : "memory");
}
#define CP_COMMIT() asm volatile("cp.async.commit_group;" ::: "memory")
#define CP_WAIT(n)  asm volatile("cp.async.wait_group %0;" :: "n"(n) : "memory")

// ---------------- conversion kernels ----------------
__global__ __launch_bounds__(256) void cvt_x_kernel(
    const float* __restrict__ q, const float* __restrict__ k, const float* __restrict__ v) {
    const int z = blockIdx.y;
    const float* __restrict__ src = (z == 0) ? q : (z == 1) ? k : v;
    size_t base = (size_t)z * MTOT * DM;
    size_t i = ((size_t)blockIdx.x * 256 + threadIdx.x) * 8;
    union { __half b[8]; uint4 u; } H;
    #pragma unroll
    for (int j = 0; j < 8; j += 4) {
        float4 f = *(const float4*)(src + i + j);
        H.b[j + 0] = __float2half_rn(f.x);
        H.b[j + 1] = __float2half_rn(f.y);
        H.b[j + 2] = __float2half_rn(f.z);
        H.b[j + 3] = __float2half_rn(f.w);
    }
    *(uint4*)(g_x + base + i) = H.u;
}

// W[w][h][k][e] -> g_wt[w][(h*64+e)][k]
__global__ __launch_bounds__(256) void cvt_wqkv_kernel(
    const float* __restrict__ wq, const float* __restrict__ wk, const float* __restrict__ wv) {
    __shared__ float s[32][33];
    const int w = blockIdx.z >> 4, hh = blockIdx.z & 15;
    const float* __restrict__ W = ((w == 0) ? wq : (w == 1) ? wk : wv) + (size_t)hh * DM * DH;
    const int k0 = blockIdx.x * 32, e0 = blockIdx.y * 32;
    const int tx = threadIdx.x, ty = threadIdx.y;
    #pragma unroll
    for (int i = 0; i < 4; i++)
        s[ty + 8 * i][tx] = W[(size_t)(k0 + ty + 8 * i) * DH + e0 + tx];
    __syncthreads();
    size_t dbase = (size_t)w * DM * DM;
    #pragma unroll
    for (int i = 0; i < 4; i++) {
        size_t o = dbase + (size_t)(hh * 64 + e0 + ty + 8 * i) * DM + k0 + tx;
        g_wt[o] = __float2half_rn(s[tx][ty + 8 * i]);
    }
}

// WO[k][d] -> g_wot[d][k]
__global__ __launch_bounds__(256) void cvt_wo_kernel(const float* __restrict__ W) {
    __shared__ float s[32][33];
    const int k0 = blockIdx.x * 32, d0 = blockIdx.y * 32;
    const int tx = threadIdx.x, ty = threadIdx.y;
    #pragma unroll
    for (int i = 0; i < 4; i++)
        s[ty + 8 * i][tx] = W[(size_t)(k0 + ty + 8 * i) * DM + d0 + tx];
    __syncthreads();
    #pragma unroll
    for (int i = 0; i < 4; i++) {
        size_t o = (size_t)(d0 + ty + 8 * i) * DM + k0 + tx;
        g_wot[o] = __float2half_rn(s[tx][ty + 8 * i]);
    }
}

// ---------------- fp16 1-term GEMM: C[128x128] = X @ W^T (+bias) ----------------
// 256 threads (8 warps: 4M x 2N; warp tile 32m x 64n). K-chunk 64.
// Stage 32KB: A@0 B@16K. 2 stages = 64KB dynamic. 2 CTAs/SM.
#define PJ_STAGE 32768

__device__ __forceinline__ void proj_copy(
    const __half* __restrict__ X, const __half* __restrict__ W,
    uint32_t sb, int st, int m0, int n0, int k0, int t)
{
    #pragma unroll
    for (int u = 0; u < 4; u++) {
        int idx = u * 256 + t;
        int row = idx >> 3, c = idx & 7;
        uint32_t so = SWZ128((row << 7) + (c << 4));
        cpa16(sb + st + so,         X + (size_t)(m0 + row) * DM + k0 + c * 8);
        cpa16(sb + st + 16384 + so, W + (size_t)(n0 + row) * DM + k0 + c * 8);
    }
}

__device__ __forceinline__ void proj_compute(uint32_t sb, int st, int lane,
                                             int wm, int wn, float acc[2][8][4])
{
    #pragma unroll
    for (int ks = 0; ks < 4; ks++) {
        uint32_t aH[2][4];
        #pragma unroll
        for (int mt = 0; mt < 2; mt++)
            ldsm4(aH[mt], fraddr(sb + st, lane, wm + mt * 16, 2 * ks));
        #pragma unroll
        for (int np = 0; np < 4; np++) {
            uint32_t bH[4];
            ldsm4(bH, fraddr(sb + st + 16384, lane, wn + np * 16, 2 * ks));
            mma_f16(acc[0][2*np],   aH[0], bH[0], bH[2]);
            mma_f16(acc[0][2*np+1], aH[0], bH[1], bH[3]);
            mma_f16(acc[1][2*np],   aH[1], bH[0], bH[2]);
            mma_f16(acc[1][2*np+1], aH[1], bH[1], bH[3]);
        }
    }
}

// mode: 0=Q (scale, fp16), 1=K (fp16), 2=V (fp16 transposed), 3=fp32 out
__device__ __forceinline__ void proj_core(
    const __half* __restrict__ X, const __half* __restrict__ W,
    const float* __restrict__ bias,
    __half* __restrict__ Oh, float* __restrict__ Of,
    char* sm, int m0, int n0, int mode)
{
    const int t = threadIdx.x, lane = t & 31, w = t >> 5;
    const uint32_t sb = smem_u32(sm);
    const int wm = (w & 3) * 32, wn = (w >> 2) * 64;
    float acc[2][8][4] = {};

    proj_copy(X, W, sb, 0, m0, n0, 0, t);
    CP_COMMIT();

    for (int kc = 0; kc < 16; kc++) {
        if (kc + 1 < 16) {
            proj_copy(X, W, sb, ((kc + 1) & 1) * PJ_STAGE, m0, n0, (kc + 1) * 64, t);
            CP_COMMIT();
            CP_WAIT(1);
        } else {
            CP_WAIT(0);
        }
        __syncthreads();
        proj_compute(sb, (kc & 1) * PJ_STAGE, lane, wm, wn, acc);
        __syncthreads();
    }

    const float scale = (mode == 0) ? QSCALE : 1.0f;
    #pragma unroll
    for (int mt = 0; mt < 2; mt++)
        #pragma unroll
        for (int np = 0; np < 8; np++)
            #pragma unroll
            for (int h2 = 0; h2 < 2; h2++) {
                int m = m0 + wm + mt * 16 + (lane >> 2) + h2 * 8;
                int n = n0 + wn + np * 8 + 2 * (lane & 3);
                float v0 = (acc[mt][np][h2 * 2]     + bias[n])     * scale;
                float v1 = (acc[mt][np][h2 * 2 + 1] + bias[n + 1]) * scale;
                if (mode == 3) {
                    *(float2*)(Of + (size_t)m * DM + n) = make_float2(v0, v1);
                } else if (mode == 2) {
                    int bb = m >> 11, seq = m & 2047;
                    size_t o0 = ((size_t)(bb * NH + (n >> 6)) * DH + (n & 63)) * SEQ + seq;
                    size_t o1 = ((size_t)(bb * NH + ((n+1) >> 6)) * DH + ((n+1) & 63)) * SEQ + seq;
                    Oh[o0] = __float2half_rn(v0);
                    Oh[o1] = __float2half_rn(v1);
                } else {
                    __half2 hp = __floats2half2_rn(v0, v1);
                    *(uint32_t*)(Oh + (size_t)m * DM + n) = *(uint32_t*)&hp;
                }
            }
}

__global__ __launch_bounds__(256, 2) void qkv_proj_mma(const float* bq, const float* bk,
                                                       const float* bv) {
    extern __shared__ char sm[];
    const int z = blockIdx.z;
    proj_core(g_x + (size_t)z * MTOT * DM, g_wt + (size_t)z * DM * DM,
              (z == 0) ? bq : (z == 1) ? bk : bv,
              (z == 0) ? g_q : (z == 1) ? g_k : g_vt,
              nullptr, sm, blockIdx.y * 128, blockIdx.x * 128, z);
}

__global__ __launch_bounds__(256, 2) void out_proj_mma(const float* bo, float* out) {
    extern __shared__ char sm[];
    proj_core(g_z, g_wot, bo, nullptr, out,
              sm, blockIdx.y * 128, blockIdx.x * 128, 3);
}

// ---------------- FA2 attention: single fp16, 2-stage K/V, 2 CTAs/SM ----------------
// smem: Q@0 (16K); stage s @ 16K+16K*s: K 0, V 8K. 48KB total.
#define AT_ST0 16384
#define AT_SS  16384

__device__ __forceinline__ void attn_copy(uint32_t sb, int kb, int b, int hd, int t) {
    const int st = AT_ST0 + (kb & 1) * AT_SS;
    const int k0 = kb * 64;
    #pragma unroll
    for (int u = 0; u < 2; u++) {
        int idx = u * 256 + t;
        int row = idx >> 3, c = idx & 7;
        uint32_t so = SWZ128((row << 7) + (c << 4));
        cpa16(sb + st + so,
              g_k + (size_t)(b * SEQ + k0 + row) * DM + hd * DH + c * 8);
        cpa16(sb + st + 8192 + so,
              g_vt + ((size_t)((b * NH + hd) * DH + row)) * SEQ + k0 + c * 8);
    }
}

__global__ __launch_bounds__(256, 2) void attn_mma() {
    extern __shared__ char sm[];
    const uint32_t sb = smem_u32(sm);
    const int t = threadIdx.x, lane = t & 31, w = t >> 5;
    const int qb = (gridDim.x - 1) - blockIdx.x;    // largest-first
    const int hd = blockIdx.y, b = blockIdx.z;
    const int q0 = qb * 128, wq = w * 16;
    const int nkb = 2 * qb + 2;

    attn_copy(sb, 0, b, hd, t);
    CP_COMMIT();

    // Q tile (128 x 64 fp16), plain stores (each thread: half a row)
    {
        int r = t >> 1, half = t & 1;
        const __half* __restrict__ src =
            g_q + (size_t)(b * SEQ + q0 + r) * DM + hd * DH + half * 32;
        #pragma unroll
        for (int i = 0; i < 4; i++)
            *(uint4*)(sm + SWZ128((r << 7) + ((half * 4 + i) << 4))) =
                *(const uint4*)(src + i * 8);
    }
    __syncthreads();

    uint32_t qH[4][4];
    #pragma unroll
    for (int ks = 0; ks < 4; ks++)
        ldsm4(qH[ks], fraddr(sb, lane, wq, 2 * ks));

    float oacc[8][4] = {};
    float lsum[2] = {0.0f, 0.0f};

    for (int kb = 0; kb < nkb; kb++) {
        const int k0 = kb * 64;
        const int st = AT_ST0 + (kb & 1) * AT_SS;
        if (kb + 1 < nkb) {
            attn_copy(sb, kb + 1, b, hd, t);
            CP_COMMIT();
            CP_WAIT(1);
        } else {
            CP_WAIT(0);
        }
        __syncthreads();

        // S = Q K^T (1 term)
        float sacc[8][4] = {};
        #pragma unroll
        for (int ds = 0; ds < 4; ds++)
            #pragma unroll
            for (int np = 0; np < 4; np++) {
                uint32_t kH[4];
                ldsm4(kH, fraddr(sb + st, lane, np * 16, 2 * ds));
                mma_f16(sacc[2*np],   qH[ds], kH[0], kH[2]);
                mma_f16(sacc[2*np+1], qH[ds], kH[1], kH[3]);
            }

        // causal mask (diagonal tiles only)
        if (kb >= 2 * qb) {
            #pragma unroll
            for (int np = 0; np < 8; np++)
                #pragma unroll
                for (int j = 0; j < 4; j++) {
                    int kg = k0 + np * 8 + 2 * (lane & 3) + (j & 1);
                    int qg = q0 + wq + (lane >> 2) + (j >> 1) * 8;
                    if (kg > qg) sacc[np][j] = -30000.0f;
                }
        }

        // f16x2 exp2; accumulate l in f16x2
        uint32_t pe[8][2];
        uint32_t la0 = 0, la1 = 0;
        #pragma unroll
        for (int np = 0; np < 8; np++) {
            pe[np][0] = h2exp2(sacc[np][0], sacc[np][1]);
            pe[np][1] = h2exp2(sacc[np][2], sacc[np][3]);
            la0 = hadd2(la0, pe[np][0]);
            la1 = hadd2(la1, pe[np][1]);
        }
        {
            float2 f0 = __half22float2(*reinterpret_cast<__half2*>(&la0));
            float2 f1 = __half22float2(*reinterpret_cast<__half2*>(&la1));
            lsum[0] += f0.x + f0.y;
            lsum[1] += f1.x + f1.y;
        }

        // PV: P fp16 (A-frag = pe), V single fp16
        #pragma unroll
        for (int ks = 0; ks < 4; ks++) {
            uint32_t pf[4] = { pe[2*ks][0], pe[2*ks][1], pe[2*ks+1][0], pe[2*ks+1][1] };
            #pragma unroll
            for (int dp = 0; dp < 4; dp++) {
                uint32_t vH[4];
                ldsm4(vH, fraddr(sb + st + 8192, lane, dp * 16, 2 * ks));
                mma_f16(oacc[2*dp],   pf, vH[0], vH[2]);
                mma_f16(oacc[2*dp+1], pf, vH[1], vH[3]);
            }
        }
        __syncthreads();
    }

    #pragma unroll
    for (int i = 0; i < 2; i++) {
        lsum[i] += __shfl_xor_sync(0xffffffffu, lsum[i], 1);
        lsum[i] += __shfl_xor_sync(0xffffffffu, lsum[i], 2);
    }
    float inv0 = 1.0f / lsum[0], inv1 = 1.0f / lsum[1];

    // z = O / l, single fp16, [b*SEQ+q][hd*64+d]
    #pragma unroll
    for (int np = 0; np < 8; np++)
        #pragma unroll
        for (int h2 = 0; h2 < 2; h2++) {
            int q = q0 + wq + (lane >> 2) + h2 * 8;
            int d = np * 8 + 2 * (lane & 3);
            float inv = h2 ? inv1 : inv0;
            __half2 hp = __floats2half2_rn(oacc[np][h2 * 2] * inv,
                                           oacc[np][h2 * 2 + 1] * inv);
            size_t o = (size_t)(b * SEQ + q) * DM + hd * DH + d;
            *(uint32_t*)(g_z + o) = *(uint32_t*)&hp;
        }
}

// ---------------------------------------------------------------------------
extern "C" void kernel_launch(void* const* d_in, const int* in_sizes, int n_in,
                              void* d_out, int out_size)
{
    const float* qin = (const float*)d_in[0];
    const float* kin = (const float*)d_in[1];
    const float* vin = (const float*)d_in[2];
    const float* WQ  = (const float*)d_in[3];
    const float* WK  = (const float*)d_in[4];
    const float* WV  = (const float*)d_in[5];
    const float* WO  = (const float*)d_in[6];
    const float* bQ  = (const float*)d_in[7];
    const float* bK  = (const float*)d_in[8];
    const float* bV  = (const float*)d_in[9];
    const float* bO  = (const float*)d_in[10];
    float* out = (float*)d_out;

    cudaFuncSetAttribute(qkv_proj_mma, cudaFuncAttributeMaxDynamicSharedMemorySize, 65536);
    cudaFuncSetAttribute(out_proj_mma, cudaFuncAttributeMaxDynamicSharedMemorySize, 65536);
    cudaFuncSetAttribute(attn_mma,     cudaFuncAttributeMaxDynamicSharedMemorySize, 49152);

    cvt_x_kernel<<<dim3(MTOT * DM / 8 / 256, 3), 256>>>(qin, kin, vin);
    cvt_wqkv_kernel<<<dim3(32, 2, 48), dim3(32, 8)>>>(WQ, WK, WV);
    cvt_wo_kernel<<<dim3(32, 32), dim3(32, 8)>>>(WO);

    qkv_proj_mma<<<dim3(DM / 128, MTOT / 128, 3), 256, 65536>>>(bQ, bK, bV);
    attn_mma<<<dim3(SEQ / 128, NH, BATCH), 256, 49152>>>();
    out_proj_mma<<<dim3(DM / 128, MTOT / 128), 256, 65536>>>(bO, out);
}